// round 1
// baseline (speedup 1.0000x reference)
#include <cuda_runtime.h>
#include <cstdint>

// Shapes (fixed by the problem)
#define TT 16
#define CC 768
#define SS 2048
#define NHEAD 12
#define HDIM 64
#define NQKV 2304

// Scratch (device globals; no allocation allowed)
__device__ float g_invrms[TT * NHEAD];                 // 192
__device__ float g_qkv[(size_t)32768 * NQKV];          // 302 MB: [m=t*2048+s][n]
__device__ float g_att[(size_t)TT * CC * SS];          // 100 MB: [t][c][s]

// ---------------- packed f32x2 helpers ----------------
__device__ __forceinline__ unsigned long long pack2(float lo, float hi) {
    unsigned long long r;
    asm("mov.b64 %0, {%1, %2};" : "=l"(r) : "f"(lo), "f"(hi));
    return r;
}
__device__ __forceinline__ float2 unpack2(unsigned long long v) {
    float2 r;
    asm("mov.b64 {%0, %1}, %2;" : "=f"(r.x), "=f"(r.y) : "l"(v));
    return r;
}
__device__ __forceinline__ void ffma2(unsigned long long& d, unsigned long long a, unsigned long long b) {
    asm("fma.rn.f32x2 %0, %1, %2, %0;" : "+l"(d) : "l"(a), "l"(b));
}

// ---------------- 1) group RMS: invrms per (t, group) ----------------
__global__ void rms_kernel(const float* __restrict__ x) {
    int b = blockIdx.x;  // b = t*12 + g ; channels of one group are contiguous
    const float4* p = (const float4*)(x + (size_t)b * 64 * SS);
    float s = 0.f;
    for (int i = threadIdx.x; i < (64 * SS) / 4; i += blockDim.x) {
        float4 v = p[i];
        s += v.x * v.x + v.y * v.y + v.z * v.z + v.w * v.w;
    }
    #pragma unroll
    for (int m = 16; m; m >>= 1) s += __shfl_xor_sync(0xffffffffu, s, m);
    __shared__ float red[8];
    if ((threadIdx.x & 31) == 0) red[threadIdx.x >> 5] = s;
    __syncthreads();
    if (threadIdx.x < 8) {
        s = red[threadIdx.x];
        #pragma unroll
        for (int m = 4; m; m >>= 1) s += __shfl_xor_sync(0xffu, s, m);
        if (threadIdx.x == 0)
            g_invrms[b] = rsqrtf(s * (1.0f / (64.0f * SS)) + 1e-6f);
    }
}

// ---------------- 2/4) tiled GEMM, 128x128x16, 8x8 micro, f32x2 FMA ----------------
// MODE 0: QKV GEMM.  A[m,k] = x[t][k][s] * invrms[t][k/64] * w1[k], m = t*2048+s.
//         C = g_qkv[m*2304 + n] = A@W_in^T + in_bias
// MODE 1: out GEMM.  A[m,k] = g_att[t][k][s].
//         out[(t*768+n)*2048+s] = A@W_out^T + out_bias + x[(t*768+n)*2048+s]
template <int MODE>
__global__ __launch_bounds__(256, 2)
void gemm_kernel(const float* __restrict__ x, const float* __restrict__ W,
                 const float* __restrict__ bias, const float* __restrict__ w1,
                 float* __restrict__ Cout, int Nn) {
    __shared__ float As[16][128];
    __shared__ float Bs[16][132];

    const int m0 = blockIdx.y * 128;
    const int n0 = blockIdx.x * 128;
    const int t  = m0 >> 11;
    const int s0 = m0 & 2047;
    const int tid = threadIdx.x;

    const int tm = (tid & 15) * 8;
    const int tn = (tid >> 4) * 8;

    const float* Asrc = (MODE == 0) ? x : g_att;

    unsigned long long acc2[8][4];
    #pragma unroll
    for (int i = 0; i < 8; i++)
        #pragma unroll
        for (int j = 0; j < 4; j++) acc2[i][j] = 0ull;

    const int kk0 = tid >> 5;        // 0..7
    const int mq  = (tid & 31) * 4;  // 0..124

    for (int k0 = 0; k0 < CC; k0 += 16) {
        // A tile: m-contiguous source
        #pragma unroll
        for (int r = 0; r < 2; r++) {
            int kk = kk0 + r * 8;
            int k  = k0 + kk;
            float scale = 1.0f;
            if (MODE == 0) scale = g_invrms[t * NHEAD + (k >> 6)] * __ldg(&w1[k]);
            const float4 v = *(const float4*)(Asrc + ((size_t)(t * CC + k)) * SS + s0 + mq);
            As[kk][mq + 0] = v.x * scale;
            As[kk][mq + 1] = v.y * scale;
            As[kk][mq + 2] = v.z * scale;
            As[kk][mq + 3] = v.w * scale;
        }
        // B tile: W is [N][K] row-major; store transposed [k][n]
        #pragma unroll
        for (int q = 0; q < 2; q++) {
            int idx = tid * 2 + q;          // 0..511
            int nn  = idx >> 2;             // 0..127
            int kq  = (idx & 3) * 4;        // 0,4,8,12
            const float4 v = *(const float4*)(W + (size_t)(n0 + nn) * CC + k0 + kq);
            Bs[kq + 0][nn] = v.x;
            Bs[kq + 1][nn] = v.y;
            Bs[kq + 2][nn] = v.z;
            Bs[kq + 3][nn] = v.w;
        }
        __syncthreads();

        #pragma unroll
        for (int kk = 0; kk < 16; kk++) {
            const float4 a0 = *(const float4*)&As[kk][tm];
            const float4 a1 = *(const float4*)&As[kk][tm + 4];
            const float4 b0 = *(const float4*)&Bs[kk][tn];
            const float4 b1 = *(const float4*)&Bs[kk][tn + 4];
            unsigned long long bb[4] = {pack2(b0.x, b0.y), pack2(b0.z, b0.w),
                                        pack2(b1.x, b1.y), pack2(b1.z, b1.w)};
            float av[8] = {a0.x, a0.y, a0.z, a0.w, a1.x, a1.y, a1.z, a1.w};
            #pragma unroll
            for (int i = 0; i < 8; i++) {
                unsigned long long aa = pack2(av[i], av[i]);
                #pragma unroll
                for (int j = 0; j < 4; j++) ffma2(acc2[i][j], aa, bb[j]);
            }
        }
        __syncthreads();
    }

    // epilogue
    float bv[8];
    #pragma unroll
    for (int j = 0; j < 8; j++) bv[j] = bias[n0 + tn + j];

    if (MODE == 0) {
        #pragma unroll
        for (int i = 0; i < 8; i++) {
            float* cp = g_qkv + (size_t)(m0 + tm + i) * Nn + n0 + tn;
            float2 v0 = unpack2(acc2[i][0]);
            float2 v1 = unpack2(acc2[i][1]);
            float2 v2 = unpack2(acc2[i][2]);
            float2 v3 = unpack2(acc2[i][3]);
            float4 o0 = make_float4(v0.x + bv[0], v0.y + bv[1], v1.x + bv[2], v1.y + bv[3]);
            float4 o1 = make_float4(v2.x + bv[4], v2.y + bv[5], v3.x + bv[6], v3.y + bv[7]);
            *(float4*)(cp)     = o0;
            *(float4*)(cp + 4) = o1;
        }
    } else {
        #pragma unroll
        for (int j = 0; j < 8; j++) {
            int n = n0 + tn + j;
            size_t base = ((size_t)(t * CC + n)) * SS + s0 + tm;
            #pragma unroll
            for (int i = 0; i < 8; i++) {
                float2 v = unpack2(acc2[i][j >> 1]);
                float val = (j & 1) ? v.y : v.x;
                Cout[base + i] = val + bv[j] + x[base + i];
            }
        }
    }
}

// ---------------- 3) attention per (head, spatial) ----------------
__global__ __launch_bounds__(256)
void attn_kernel(const float* __restrict__ qs, const float* __restrict__ qb,
                 const float* __restrict__ ks, const float* __restrict__ kb,
                 const float* __restrict__ relb) {
    __shared__ float sq[16][193];   // [t][0:64)=q, [64:128)=k, [128:192)=v  (pad 193)
    __shared__ float attn[16][17];

    const int head = blockIdx.x;
    const int s    = blockIdx.y;
    const int tid  = threadIdx.x;

    // load 16 x 192
    for (int i = tid; i < 16 * 192; i += 256) {
        int tt = i / 192, c = i % 192;
        sq[tt][c] = g_qkv[((size_t)(tt * SS + s)) * NQKV + head * 192 + c];
    }
    __syncthreads();

    // layernorm q rows (groups 0..15) and k rows (groups 16..31), 8 lanes per row
    {
        int g   = tid >> 3;
        int l   = tid & 7;
        int row = g & 15;
        int off = (g < 16) ? 0 : 64;
        float sum = 0.f, ssq = 0.f;
        #pragma unroll
        for (int u = 0; u < 8; u++) {
            float v = sq[row][off + l + u * 8];
            sum += v; ssq += v * v;
        }
        #pragma unroll
        for (int m = 4; m; m >>= 1) {
            sum += __shfl_xor_sync(0xffffffffu, sum, m, 8);
            ssq += __shfl_xor_sync(0xffffffffu, ssq, m, 8);
        }
        float mu  = sum * (1.0f / 64.0f);
        float var = ssq * (1.0f / 64.0f) - mu * mu;
        float inv = rsqrtf(var + 1e-6f);
        const float* sc = (g < 16) ? qs : ks;
        const float* bi = (g < 16) ? qb : kb;
        #pragma unroll
        for (int u = 0; u < 8; u++) {
            int c = l + u * 8;
            sq[row][off + c] = (sq[row][off + c] - mu) * inv * sc[c] + bi[c];
        }
    }
    __syncthreads();

    // scores + softmax (thread (i,j))
    {
        int i = tid >> 4, j = tid & 15;
        float dot = 0.f;
        #pragma unroll
        for (int c = 0; c < 64; c++) dot += sq[i][c] * sq[j][64 + c];

        int rp = j - i;
        int bucket = (rp > 0) ? 16 : 0;
        int n = abs(rp);
        if (n < 8) bucket += n;
        else {
            int large = 8 + (int)(__logf((float)n * 0.125f) * (8.0f / 2.7725887222397811f));
            bucket += (large < 15) ? large : 15;
        }
        float sc = dot * 0.125f + relb[bucket * NHEAD + head];

        float mx = sc;
        #pragma unroll
        for (int m = 8; m; m >>= 1) mx = fmaxf(mx, __shfl_xor_sync(0xffffffffu, mx, m, 16));
        float e = __expf(sc - mx);
        float sm = e;
        #pragma unroll
        for (int m = 8; m; m >>= 1) sm += __shfl_xor_sync(0xffffffffu, sm, m, 16);
        attn[i][j] = e / sm;
    }
    __syncthreads();

    // out = attn @ v, write to g_att[t][head*64+c][s]
    #pragma unroll
    for (int l = 0; l < 4; l++) {
        int idx = tid + l * 256;
        int oi = idx >> 6, c = idx & 63;
        float acc = 0.f;
        #pragma unroll
        for (int tt = 0; tt < 16; tt++) acc += attn[oi][tt] * sq[tt][128 + c];
        g_att[((size_t)(oi * CC + head * HDIM + c)) * SS + s] = acc;
    }
}

extern "C" void kernel_launch(void* const* d_in, const int* in_sizes, int n_in,
                              void* d_out, int out_size) {
    const float* x    = (const float*)d_in[0];
    const float* w1   = (const float*)d_in[1];
    const float* Win  = (const float*)d_in[2];   // (2304,768)
    const float* binq = (const float*)d_in[3];
    const float* qsc  = (const float*)d_in[4];
    const float* qbi  = (const float*)d_in[5];
    const float* ksc  = (const float*)d_in[6];
    const float* kbi  = (const float*)d_in[7];
    const float* relb = (const float*)d_in[8];   // (32,12)
    const float* Wout = (const float*)d_in[9];   // (768,768)
    const float* bout = (const float*)d_in[10];
    float* out = (float*)d_out;

    rms_kernel<<<TT * NHEAD, 256>>>(x);
    gemm_kernel<0><<<dim3(NQKV / 128, 256), 256>>>(x, Win, binq, w1, nullptr, NQKV);
    attn_kernel<<<dim3(NHEAD, SS), 256>>>(qsc, qbi, ksc, kbi, relb);
    gemm_kernel<1><<<dim3(CC / 128, 256), 256>>>(x, Wout, bout, nullptr, out, CC);
}

// round 3
// speedup vs baseline: 1.8873x; 1.8873x over previous
#include <cuda_runtime.h>
#include <cstdint>

#define TT 16
#define CC 768
#define SS 2048
#define NHEAD 12
#define HDIM 64
#define NQKV 2304

// Scratch (device globals; no allocation allowed)
__device__ float g_invrms[TT * NHEAD];
__device__ float g_qkv[(size_t)32768 * NQKV];          // [m=t*2048+s][n]
__device__ float g_att[(size_t)TT * CC * SS];          // [t][c][s]

__device__ __forceinline__ uint32_t to_tf32(float x) {
    uint32_t o;
    asm("cvt.rna.tf32.f32 %0, %1;" : "=r"(o) : "f"(x));
    return o;
}

__device__ __forceinline__ void mma_tf32(float* d, const uint32_t* a, const uint32_t* b) {
    asm volatile(
        "mma.sync.aligned.m16n8k8.row.col.f32.tf32.tf32.f32 "
        "{%0,%1,%2,%3}, {%4,%5,%6,%7}, {%8,%9}, {%0,%1,%2,%3};"
        : "+f"(d[0]), "+f"(d[1]), "+f"(d[2]), "+f"(d[3])
        : "r"(a[0]), "r"(a[1]), "r"(a[2]), "r"(a[3]), "r"(b[0]), "r"(b[1]));
}

// ---------------- 1) group RMS ----------------
__global__ void rms_kernel(const float* __restrict__ x) {
    int b = blockIdx.x;
    const float4* p = (const float4*)(x + (size_t)b * 64 * SS);
    float s = 0.f;
    for (int i = threadIdx.x; i < (64 * SS) / 4; i += blockDim.x) {
        float4 v = p[i];
        s += v.x * v.x + v.y * v.y + v.z * v.z + v.w * v.w;
    }
    #pragma unroll
    for (int m = 16; m; m >>= 1) s += __shfl_xor_sync(0xffffffffu, s, m);
    __shared__ float red[8];
    if ((threadIdx.x & 31) == 0) red[threadIdx.x >> 5] = s;
    __syncthreads();
    if (threadIdx.x < 8) {
        s = red[threadIdx.x];
        #pragma unroll
        for (int m = 4; m; m >>= 1) s += __shfl_xor_sync(0xffu, s, m);
        if (threadIdx.x == 0)
            g_invrms[b] = rsqrtf(s * (1.0f / (64.0f * SS)) + 1e-6f);
    }
}

// ---------------- 2/4) mma.sync tf32 GEMM, 128x128 tile, K-chunk 16, double-buffered ----------------
// MODE 0: A = x * invrms * w1 ; C -> g_qkv[m][n] (+bias)
// MODE 1: A = g_att           ; C -> out[(t*768+n)*2048+s] (+bias + residual)
#define NKIT 48

template <int MODE>
__global__ __launch_bounds__(256, 2)
void mma_gemm(const float* __restrict__ x, const float* __restrict__ W,
              const float* __restrict__ bias, const float* __restrict__ w1,
              float* __restrict__ Cout, int Nn) {
    __shared__ uint32_t As[2][16][132];   // [buf][k][m]
    __shared__ uint32_t Bs[2][16][132];   // [buf][k][n]

    const int tid  = threadIdx.x;
    const int wid  = tid >> 5;
    const int lane = tid & 31;
    const int wm   = (wid & 1) * 64;       // warp m offset
    const int wn   = (wid >> 1) * 32;      // warp n offset
    const int lq   = lane >> 2;            // 0..7
    const int lr   = lane & 3;             // 0..3

    const int m0 = blockIdx.y * 128;
    const int n0 = blockIdx.x * 128;
    const int t  = m0 >> 11;
    const int s0 = m0 & 2047;

    const float* Asrc = (MODE == 0) ? x : g_att;

    // A loader indices: two rows kk and kk+8, m-segment of 4
    const int kkA = tid >> 5;              // 0..7
    const int mA  = (tid & 31) * 4;
    // B loader indices: per q in {0,1}: idx = tid*2+q -> nn, kq
    const int nnB0 = (tid * 2)     >> 2;
    const int kqB0 = ((tid * 2) & 3) * 4;
    const int nnB1 = (tid * 2 + 1) >> 2;
    const int kqB1 = ((tid * 2 + 1) & 3) * 4;

    float acc[4][4][4];
    #pragma unroll
    for (int i = 0; i < 4; i++)
        #pragma unroll
        for (int j = 0; j < 4; j++)
            #pragma unroll
            for (int c = 0; c < 4; c++) acc[i][j][c] = 0.f;

    // fetch tile k0 into registers
    float4 apre[2], bpre[2];
    auto fetch = [&](int k0) {
        #pragma unroll
        for (int r = 0; r < 2; r++) {
            int k = k0 + kkA + r * 8;
            float4 v = *(const float4*)(Asrc + ((size_t)(t * CC + k)) * SS + s0 + mA);
            if (MODE == 0) {
                float sc = g_invrms[t * NHEAD + (k >> 6)] * __ldg(&w1[k]);
                v.x *= sc; v.y *= sc; v.z *= sc; v.w *= sc;
            }
            apre[r] = v;
        }
        bpre[0] = *(const float4*)(W + (size_t)(n0 + nnB0) * CC + k0 + kqB0);
        bpre[1] = *(const float4*)(W + (size_t)(n0 + nnB1) * CC + k0 + kqB1);
    };
    auto store = [&](int p) {
        #pragma unroll
        for (int r = 0; r < 2; r++) {
            int kk = kkA + r * 8;
            As[p][kk][mA + 0] = to_tf32(apre[r].x);
            As[p][kk][mA + 1] = to_tf32(apre[r].y);
            As[p][kk][mA + 2] = to_tf32(apre[r].z);
            As[p][kk][mA + 3] = to_tf32(apre[r].w);
        }
        Bs[p][kqB0 + 0][nnB0] = to_tf32(bpre[0].x);
        Bs[p][kqB0 + 1][nnB0] = to_tf32(bpre[0].y);
        Bs[p][kqB0 + 2][nnB0] = to_tf32(bpre[0].z);
        Bs[p][kqB0 + 3][nnB0] = to_tf32(bpre[0].w);
        Bs[p][kqB1 + 0][nnB1] = to_tf32(bpre[1].x);
        Bs[p][kqB1 + 1][nnB1] = to_tf32(bpre[1].y);
        Bs[p][kqB1 + 2][nnB1] = to_tf32(bpre[1].z);
        Bs[p][kqB1 + 3][nnB1] = to_tf32(bpre[1].w);
    };

    fetch(0);
    store(0);
    __syncthreads();

    for (int i = 0; i < NKIT; i++) {
        const int p = i & 1;
        if (i + 1 < NKIT) fetch((i + 1) * 16);

        #pragma unroll
        for (int ks = 0; ks < 2; ks++) {
            uint32_t af[4][4], bf[4][2];
            const int kb = ks * 8;
            #pragma unroll
            for (int im = 0; im < 4; im++) {
                int row = wm + im * 16 + lq;
                af[im][0] = As[p][kb + lr][row];
                af[im][1] = As[p][kb + lr][row + 8];
                af[im][2] = As[p][kb + lr + 4][row];
                af[im][3] = As[p][kb + lr + 4][row + 8];
            }
            #pragma unroll
            for (int in = 0; in < 4; in++) {
                int col = wn + in * 8 + lq;
                bf[in][0] = Bs[p][kb + lr][col];
                bf[in][1] = Bs[p][kb + lr + 4][col];
            }
            #pragma unroll
            for (int im = 0; im < 4; im++)
                #pragma unroll
                for (int in = 0; in < 4; in++)
                    mma_tf32(acc[im][in], af[im], bf[in]);
        }

        if (i + 1 < NKIT) {
            store(p ^ 1);
            __syncthreads();
        }
    }

    // epilogue
    #pragma unroll
    for (int im = 0; im < 4; im++) {
        const int r_lo = wm + im * 16 + lq;
        const int r_hi = r_lo + 8;
        #pragma unroll
        for (int in = 0; in < 4; in++) {
            const int col = n0 + wn + in * 8 + lr * 2;
            const float b0 = bias[col], b1 = bias[col + 1];
            if (MODE == 0) {
                float2 v0 = make_float2(acc[im][in][0] + b0, acc[im][in][1] + b1);
                float2 v1 = make_float2(acc[im][in][2] + b0, acc[im][in][3] + b1);
                *(float2*)(g_qkv + (size_t)(m0 + r_lo) * Nn + col) = v0;
                *(float2*)(g_qkv + (size_t)(m0 + r_hi) * Nn + col) = v1;
            } else {
                size_t o0 = ((size_t)(t * CC + col)) * SS + s0;
                size_t o1 = ((size_t)(t * CC + col + 1)) * SS + s0;
                Cout[o0 + r_lo] = acc[im][in][0] + b0 + x[o0 + r_lo];
                Cout[o1 + r_lo] = acc[im][in][1] + b1 + x[o1 + r_lo];
                Cout[o0 + r_hi] = acc[im][in][2] + b0 + x[o0 + r_hi];
                Cout[o1 + r_hi] = acc[im][in][3] + b1 + x[o1 + r_hi];
            }
        }
    }
}

// ---------------- 3) attention per (head, spatial) ----------------
__global__ __launch_bounds__(256)
void attn_kernel(const float* __restrict__ qs, const float* __restrict__ qb,
                 const float* __restrict__ ks, const float* __restrict__ kb,
                 const float* __restrict__ relb) {
    __shared__ float sq[16][193];
    __shared__ float attn[16][17];

    const int head = blockIdx.x;
    const int s    = blockIdx.y;
    const int tid  = threadIdx.x;

    for (int i = tid; i < 16 * 192; i += 256) {
        int tt = i / 192, c = i % 192;
        sq[tt][c] = g_qkv[((size_t)(tt * SS + s)) * NQKV + head * 192 + c];
    }
    __syncthreads();

    {
        int g   = tid >> 3;
        int l   = tid & 7;
        int row = g & 15;
        int off = (g < 16) ? 0 : 64;
        float sum = 0.f, ssq = 0.f;
        #pragma unroll
        for (int u = 0; u < 8; u++) {
            float v = sq[row][off + l + u * 8];
            sum += v; ssq += v * v;
        }
        #pragma unroll
        for (int m = 4; m; m >>= 1) {
            sum += __shfl_xor_sync(0xffffffffu, sum, m, 8);
            ssq += __shfl_xor_sync(0xffffffffu, ssq, m, 8);
        }
        float mu  = sum * (1.0f / 64.0f);
        float var = ssq * (1.0f / 64.0f) - mu * mu;
        float inv = rsqrtf(var + 1e-6f);
        const float* sc = (g < 16) ? qs : ks;
        const float* bi = (g < 16) ? qb : kb;
        #pragma unroll
        for (int u = 0; u < 8; u++) {
            int c = l + u * 8;
            sq[row][off + c] = (sq[row][off + c] - mu) * inv * sc[c] + bi[c];
        }
    }
    __syncthreads();

    {
        int i = tid >> 4, j = tid & 15;
        float dot = 0.f;
        #pragma unroll
        for (int c = 0; c < 64; c++) dot += sq[i][c] * sq[j][64 + c];

        int rp = j - i;
        int bucket = (rp > 0) ? 16 : 0;
        int n = abs(rp);
        if (n < 8) bucket += n;
        else {
            int large = 8 + (int)(__logf((float)n * 0.125f) * (8.0f / 2.7725887222397811f));
            bucket += (large < 15) ? large : 15;
        }
        float sc = dot * 0.125f + relb[bucket * NHEAD + head];

        float mx = sc;
        #pragma unroll
        for (int m = 8; m; m >>= 1) mx = fmaxf(mx, __shfl_xor_sync(0xffffffffu, mx, m, 16));
        float e = __expf(sc - mx);
        float sm = e;
        #pragma unroll
        for (int m = 8; m; m >>= 1) sm += __shfl_xor_sync(0xffffffffu, sm, m, 16);
        attn[i][j] = e / sm;
    }
    __syncthreads();

    #pragma unroll
    for (int l = 0; l < 4; l++) {
        int idx = tid + l * 256;
        int oi = idx >> 6, c = idx & 63;
        float acc = 0.f;
        #pragma unroll
        for (int tt = 0; tt < 16; tt++) acc += attn[oi][tt] * sq[tt][128 + c];
        g_att[((size_t)(oi * CC + head * HDIM + c)) * SS + s] = acc;
    }
}

extern "C" void kernel_launch(void* const* d_in, const int* in_sizes, int n_in,
                              void* d_out, int out_size) {
    const float* x    = (const float*)d_in[0];
    const float* w1   = (const float*)d_in[1];
    const float* Win  = (const float*)d_in[2];
    const float* binq = (const float*)d_in[3];
    const float* qsc  = (const float*)d_in[4];
    const float* qbi  = (const float*)d_in[5];
    const float* ksc  = (const float*)d_in[6];
    const float* kbi  = (const float*)d_in[7];
    const float* relb = (const float*)d_in[8];
    const float* Wout = (const float*)d_in[9];
    const float* bout = (const float*)d_in[10];
    float* out = (float*)d_out;

    rms_kernel<<<TT * NHEAD, 256>>>(x);
    mma_gemm<0><<<dim3(NQKV / 128, 256), 256>>>(x, Win, binq, w1, nullptr, NQKV);
    attn_kernel<<<dim3(NHEAD, SS), 256>>>(qsc, qbi, ksc, kbi, relb);
    mma_gemm<1><<<dim3(CC / 128, 256), 256>>>(x, Wout, bout, nullptr, out, CC);
}

// round 4
// speedup vs baseline: 2.0437x; 1.0829x over previous
#include <cuda_runtime.h>
#include <cstdint>

#define TT 16
#define CC 768
#define SS 2048
#define NHEAD 12
#define HDIM 64
#define NQKV 2304

// Scratch (device globals; no allocation allowed)
__device__ float g_invrms[TT * NHEAD];
__device__ float g_qkv[(size_t)32768 * NQKV];          // [m=t*2048+s][n]
__device__ float g_att[(size_t)TT * CC * SS];          // [t][c][s]

__device__ __forceinline__ uint32_t to_tf32(float x) {
    uint32_t o;
    asm("cvt.rna.tf32.f32 %0, %1;" : "=r"(o) : "f"(x));
    return o;
}

__device__ __forceinline__ void mma_tf32(float* d, const uint32_t* a, const uint32_t* b) {
    asm volatile(
        "mma.sync.aligned.m16n8k8.row.col.f32.tf32.tf32.f32 "
        "{%0,%1,%2,%3}, {%4,%5,%6,%7}, {%8,%9}, {%0,%1,%2,%3};"
        : "+f"(d[0]), "+f"(d[1]), "+f"(d[2]), "+f"(d[3])
        : "r"(a[0]), "r"(a[1]), "r"(a[2]), "r"(a[3]), "r"(b[0]), "r"(b[1]));
}

// ---------------- 1) group RMS ----------------
__global__ void rms_kernel(const float* __restrict__ x) {
    int b = blockIdx.x;
    const float4* p = (const float4*)(x + (size_t)b * 64 * SS);
    float s = 0.f;
    for (int i = threadIdx.x; i < (64 * SS) / 4; i += blockDim.x) {
        float4 v = p[i];
        s += v.x * v.x + v.y * v.y + v.z * v.z + v.w * v.w;
    }
    #pragma unroll
    for (int m = 16; m; m >>= 1) s += __shfl_xor_sync(0xffffffffu, s, m);
    __shared__ float red[8];
    if ((threadIdx.x & 31) == 0) red[threadIdx.x >> 5] = s;
    __syncthreads();
    if (threadIdx.x < 8) {
        s = red[threadIdx.x];
        #pragma unroll
        for (int m = 4; m; m >>= 1) s += __shfl_xor_sync(0xffu, s, m);
        if (threadIdx.x == 0)
            g_invrms[b] = rsqrtf(s * (1.0f / (64.0f * SS)) + 1e-6f);
    }
}

// ---------------- 2/4) mma.sync tf32 GEMM ----------------
// CTA tile 128x128, 4 warps (2x2), warp tile 64x64, K-chunk 16, double-buffered.
// Conflict-free smem: As[k][136] (k-major), Bs[n][20] (n-major, untransposed).
// MODE 0: A = x * invrms * w1 ; C -> g_qkv[m][n] (+bias)
// MODE 1: A = g_att           ; C -> out[(t*768+n)*2048+s] (+bias + residual)
#define NKIT 48
#define APAD 136
#define BPAD 20

template <int MODE>
__global__ __launch_bounds__(128, 2)
void mma_gemm(const float* __restrict__ x, const float* __restrict__ W,
              const float* __restrict__ bias, const float* __restrict__ w1,
              float* __restrict__ Cout, int Nn) {
    __shared__ uint32_t As[2][16][APAD];   // [buf][k][m]
    __shared__ uint32_t Bs[2][128][BPAD];  // [buf][n][k]

    const int tid  = threadIdx.x;
    const int wid  = tid >> 5;
    const int lane = tid & 31;
    const int wm   = (wid >> 1) * 64;
    const int wn   = (wid & 1) * 64;
    const int lq   = lane >> 2;            // 0..7
    const int lr   = lane & 3;             // 0..3

    const int m0 = blockIdx.y * 128;
    const int n0 = blockIdx.x * 128;
    const int t  = m0 >> 11;
    const int s0 = m0 & 2047;

    const float* Asrc = (MODE == 0) ? x : g_att;

    // A loader: 4 k-rows (kkA + 4r), m-chunk of 4 floats
    const int kkA = tid >> 5;              // 0..3
    const int mA  = (tid & 31) * 4;
    // B loader: row nn = tid, four 16B k-chunks

    float acc[4][8][4];
    #pragma unroll
    for (int i = 0; i < 4; i++)
        #pragma unroll
        for (int j = 0; j < 8; j++)
            #pragma unroll
            for (int c = 0; c < 4; c++) acc[i][j][c] = 0.f;

    float4 apre[4], bpre[4];
    auto fetch = [&](int k0) {
        #pragma unroll
        for (int r = 0; r < 4; r++) {
            int k = k0 + kkA + r * 4;
            float4 v = *(const float4*)(Asrc + ((size_t)(t * CC + k)) * SS + s0 + mA);
            if (MODE == 0) {
                float sc = g_invrms[t * NHEAD + (k >> 6)] * __ldg(&w1[k]);
                v.x *= sc; v.y *= sc; v.z *= sc; v.w *= sc;
            }
            apre[r] = v;
        }
        const float4* wp = (const float4*)(W + (size_t)(n0 + tid) * CC + k0);
        #pragma unroll
        for (int q = 0; q < 4; q++) bpre[q] = wp[q];
    };
    auto store = [&](int p) {
        #pragma unroll
        for (int r = 0; r < 4; r++) {
            int kk = kkA + r * 4;
            *(uint4*)&As[p][kk][mA] = make_uint4(to_tf32(apre[r].x), to_tf32(apre[r].y),
                                                 to_tf32(apre[r].z), to_tf32(apre[r].w));
        }
        #pragma unroll
        for (int q = 0; q < 4; q++)
            *(uint4*)&Bs[p][tid][q * 4] = make_uint4(to_tf32(bpre[q].x), to_tf32(bpre[q].y),
                                                     to_tf32(bpre[q].z), to_tf32(bpre[q].w));
    };

    fetch(0);
    store(0);
    __syncthreads();

    for (int i = 0; i < NKIT; i++) {
        const int p = i & 1;
        if (i + 1 < NKIT) fetch((i + 1) * 16);

        #pragma unroll
        for (int ks = 0; ks < 2; ks++) {
            const int kb = ks * 8;
            uint32_t af[4][4], bf[8][2];
            #pragma unroll
            for (int im = 0; im < 4; im++) {
                int row = wm + im * 16 + lq;
                af[im][0] = As[p][kb + lr][row];
                af[im][1] = As[p][kb + lr][row + 8];
                af[im][2] = As[p][kb + lr + 4][row];
                af[im][3] = As[p][kb + lr + 4][row + 8];
            }
            #pragma unroll
            for (int in = 0; in < 8; in++) {
                int col = wn + in * 8 + lq;
                bf[in][0] = Bs[p][col][kb + lr];
                bf[in][1] = Bs[p][col][kb + lr + 4];
            }
            #pragma unroll
            for (int im = 0; im < 4; im++)
                #pragma unroll
                for (int in = 0; in < 8; in++)
                    mma_tf32(acc[im][in], af[im], bf[in]);
        }

        if (i + 1 < NKIT) {
            store(p ^ 1);
            __syncthreads();
        }
    }

    // epilogue
    #pragma unroll
    for (int im = 0; im < 4; im++) {
        const int r_lo = wm + im * 16 + lq;
        const int r_hi = r_lo + 8;
        #pragma unroll
        for (int in = 0; in < 8; in++) {
            const int col = n0 + wn + in * 8 + lr * 2;
            const float b0 = bias[col], b1 = bias[col + 1];
            if (MODE == 0) {
                *(float2*)(g_qkv + (size_t)(m0 + r_lo) * Nn + col) =
                    make_float2(acc[im][in][0] + b0, acc[im][in][1] + b1);
                *(float2*)(g_qkv + (size_t)(m0 + r_hi) * Nn + col) =
                    make_float2(acc[im][in][2] + b0, acc[im][in][3] + b1);
            } else {
                size_t o0 = ((size_t)(t * CC + col)) * SS + s0;
                size_t o1 = ((size_t)(t * CC + col + 1)) * SS + s0;
                Cout[o0 + r_lo] = acc[im][in][0] + b0 + x[o0 + r_lo];
                Cout[o1 + r_lo] = acc[im][in][1] + b1 + x[o1 + r_lo];
                Cout[o0 + r_hi] = acc[im][in][2] + b0 + x[o0 + r_hi];
                Cout[o1 + r_hi] = acc[im][in][3] + b1 + x[o1 + r_hi];
            }
        }
    }
}

// ---------------- 3) attention per (head, spatial) ----------------
__global__ __launch_bounds__(256)
void attn_kernel(const float* __restrict__ qs, const float* __restrict__ qb,
                 const float* __restrict__ ks, const float* __restrict__ kb,
                 const float* __restrict__ relb) {
    __shared__ float sq[16][193];
    __shared__ float attn[16][17];

    const int head = blockIdx.x;
    const int s    = blockIdx.y;
    const int tid  = threadIdx.x;

    for (int i = tid; i < 16 * 192; i += 256) {
        int tt = i / 192, c = i % 192;
        sq[tt][c] = g_qkv[((size_t)(tt * SS + s)) * NQKV + head * 192 + c];
    }
    __syncthreads();

    {
        int g   = tid >> 3;
        int l   = tid & 7;
        int row = g & 15;
        int off = (g < 16) ? 0 : 64;
        float sum = 0.f, ssq = 0.f;
        #pragma unroll
        for (int u = 0; u < 8; u++) {
            float v = sq[row][off + l + u * 8];
            sum += v; ssq += v * v;
        }
        #pragma unroll
        for (int m = 4; m; m >>= 1) {
            sum += __shfl_xor_sync(0xffffffffu, sum, m, 8);
            ssq += __shfl_xor_sync(0xffffffffu, ssq, m, 8);
        }
        float mu  = sum * (1.0f / 64.0f);
        float var = ssq * (1.0f / 64.0f) - mu * mu;
        float inv = rsqrtf(var + 1e-6f);
        const float* sc = (g < 16) ? qs : ks;
        const float* bi = (g < 16) ? qb : kb;
        #pragma unroll
        for (int u = 0; u < 8; u++) {
            int c = l + u * 8;
            sq[row][off + c] = (sq[row][off + c] - mu) * inv * sc[c] + bi[c];
        }
    }
    __syncthreads();

    {
        int i = tid >> 4, j = tid & 15;
        float dot = 0.f;
        #pragma unroll
        for (int c = 0; c < 64; c++) dot += sq[i][c] * sq[j][64 + c];

        int rp = j - i;
        int bucket = (rp > 0) ? 16 : 0;
        int n = abs(rp);
        if (n < 8) bucket += n;
        else {
            int large = 8 + (int)(__logf((float)n * 0.125f) * (8.0f / 2.7725887222397811f));
            bucket += (large < 15) ? large : 15;
        }
        float sc = dot * 0.125f + relb[bucket * NHEAD + head];

        float mx = sc;
        #pragma unroll
        for (int m = 8; m; m >>= 1) mx = fmaxf(mx, __shfl_xor_sync(0xffffffffu, mx, m, 16));
        float e = __expf(sc - mx);
        float sm = e;
        #pragma unroll
        for (int m = 8; m; m >>= 1) sm += __shfl_xor_sync(0xffffffffu, sm, m, 16);
        attn[i][j] = e / sm;
    }
    __syncthreads();

    #pragma unroll
    for (int l = 0; l < 4; l++) {
        int idx = tid + l * 256;
        int oi = idx >> 6, c = idx & 63;
        float acc = 0.f;
        #pragma unroll
        for (int tt = 0; tt < 16; tt++) acc += attn[oi][tt] * sq[tt][128 + c];
        g_att[((size_t)(oi * CC + head * HDIM + c)) * SS + s] = acc;
    }
}

extern "C" void kernel_launch(void* const* d_in, const int* in_sizes, int n_in,
                              void* d_out, int out_size) {
    const float* x    = (const float*)d_in[0];
    const float* w1   = (const float*)d_in[1];
    const float* Win  = (const float*)d_in[2];
    const float* binq = (const float*)d_in[3];
    const float* qsc  = (const float*)d_in[4];
    const float* qbi  = (const float*)d_in[5];
    const float* ksc  = (const float*)d_in[6];
    const float* kbi  = (const float*)d_in[7];
    const float* relb = (const float*)d_in[8];
    const float* Wout = (const float*)d_in[9];
    const float* bout = (const float*)d_in[10];
    float* out = (float*)d_out;

    rms_kernel<<<TT * NHEAD, 256>>>(x);
    mma_gemm<0><<<dim3(NQKV / 128, 256), 128>>>(x, Win, binq, w1, nullptr, NQKV);
    attn_kernel<<<dim3(NHEAD, SS), 256>>>(qsc, qbi, ksc, kbi, relb);
    mma_gemm<1><<<dim3(CC / 128, 256), 128>>>(x, Wout, bout, nullptr, out, CC);
}

// round 5
// speedup vs baseline: 2.2243x; 1.0884x over previous
#include <cuda_runtime.h>
#include <cstdint>

#define TT 16
#define CC 768
#define SS 2048
#define NHEAD 12
#define HDIM 64
#define NQKV 2304

// Scratch (device globals; no allocation allowed)
__device__ float g_invrms[TT * NHEAD];
__device__ float g_qkv[(size_t)32768 * NQKV];          // [m=t*2048+s][n]
__device__ float g_att[(size_t)TT * CC * SS];          // [t][c][s]

__device__ __forceinline__ uint32_t to_tf32(float x) {
    uint32_t o;
    asm("cvt.rna.tf32.f32 %0, %1;" : "=r"(o) : "f"(x));
    return o;
}

__device__ __forceinline__ void mma_tf32(float* d, const uint32_t* a, const uint32_t* b) {
    asm volatile(
        "mma.sync.aligned.m16n8k8.row.col.f32.tf32.tf32.f32 "
        "{%0,%1,%2,%3}, {%4,%5,%6,%7}, {%8,%9}, {%0,%1,%2,%3};"
        : "+f"(d[0]), "+f"(d[1]), "+f"(d[2]), "+f"(d[3])
        : "r"(a[0]), "r"(a[1]), "r"(a[2]), "r"(a[3]), "r"(b[0]), "r"(b[1]));
}

// ---------------- 1) group RMS ----------------
__global__ void rms_kernel(const float* __restrict__ x) {
    int b = blockIdx.x;
    const float4* p = (const float4*)(x + (size_t)b * 64 * SS);
    float s = 0.f;
    for (int i = threadIdx.x; i < (64 * SS) / 4; i += blockDim.x) {
        float4 v = p[i];
        s += v.x * v.x + v.y * v.y + v.z * v.z + v.w * v.w;
    }
    #pragma unroll
    for (int m = 16; m; m >>= 1) s += __shfl_xor_sync(0xffffffffu, s, m);
    __shared__ float red[8];
    if ((threadIdx.x & 31) == 0) red[threadIdx.x >> 5] = s;
    __syncthreads();
    if (threadIdx.x < 8) {
        s = red[threadIdx.x];
        #pragma unroll
        for (int m = 4; m; m >>= 1) s += __shfl_xor_sync(0xffu, s, m);
        if (threadIdx.x == 0)
            g_invrms[b] = rsqrtf(s * (1.0f / (64.0f * SS)) + 1e-6f);
    }
}

// ---------------- 2/4) mma.sync tf32 GEMM ----------------
// CTA tile 128x128, 8 warps (2x4), warp tile 64x32, K-chunk 16, double-buffered.
// Conflict-free smem: As[k][136] (k-major), Bs[n][20] (n-major, untransposed).
// MODE 0: A = x * invrms * w1 ; C -> g_qkv[m][n] (+bias)
// MODE 1: A = g_att           ; C -> out[(t*768+n)*2048+s] (+bias + residual)
#define NKIT 48
#define APAD 136
#define BPAD 20

template <int MODE>
__global__ __launch_bounds__(256, 2)
void mma_gemm(const float* __restrict__ x, const float* __restrict__ W,
              const float* __restrict__ bias, const float* __restrict__ w1,
              float* __restrict__ Cout, int Nn) {
    __shared__ uint32_t As[2][16][APAD];   // [buf][k][m]
    __shared__ uint32_t Bs[2][128][BPAD];  // [buf][n][k]

    const int tid  = threadIdx.x;
    const int wid  = tid >> 5;
    const int lane = tid & 31;
    const int wm   = (wid & 1) * 64;       // 2 warps over m
    const int wn   = (wid >> 1) * 32;      // 4 warps over n
    const int lq   = lane >> 2;            // 0..7
    const int lr   = lane & 3;             // 0..3

    const int m0 = blockIdx.y * 128;
    const int n0 = blockIdx.x * 128;
    const int t  = m0 >> 11;
    const int s0 = m0 & 2047;

    const float* Asrc = (MODE == 0) ? x : g_att;

    // A loader: rows kkA and kkA+8, m-chunk of 4 floats
    const int kkA = tid >> 5;              // 0..7
    const int mA  = (tid & 31) * 4;
    // B loader: row nnB, two 16B chunks at k-offset qB*8
    const int nnB = tid >> 1;              // 0..127
    const int qB  = (tid & 1) * 8;         // 0 or 8

    float acc[4][4][4];
    #pragma unroll
    for (int i = 0; i < 4; i++)
        #pragma unroll
        for (int j = 0; j < 4; j++)
            #pragma unroll
            for (int c = 0; c < 4; c++) acc[i][j][c] = 0.f;

    float4 apre[2], bpre[2];
    auto fetch = [&](int k0) {
        #pragma unroll
        for (int r = 0; r < 2; r++) {
            int k = k0 + kkA + r * 8;
            float4 v = *(const float4*)(Asrc + ((size_t)(t * CC + k)) * SS + s0 + mA);
            if (MODE == 0) {
                float sc = g_invrms[t * NHEAD + (k >> 6)] * __ldg(&w1[k]);
                v.x *= sc; v.y *= sc; v.z *= sc; v.w *= sc;
            }
            apre[r] = v;
        }
        const float4* wp = (const float4*)(W + (size_t)(n0 + nnB) * CC + k0 + qB);
        bpre[0] = wp[0];
        bpre[1] = wp[1];
    };
    auto store = [&](int p) {
        #pragma unroll
        for (int r = 0; r < 2; r++) {
            int kk = kkA + r * 8;
            *(uint4*)&As[p][kk][mA] = make_uint4(to_tf32(apre[r].x), to_tf32(apre[r].y),
                                                 to_tf32(apre[r].z), to_tf32(apre[r].w));
        }
        *(uint4*)&Bs[p][nnB][qB]     = make_uint4(to_tf32(bpre[0].x), to_tf32(bpre[0].y),
                                                  to_tf32(bpre[0].z), to_tf32(bpre[0].w));
        *(uint4*)&Bs[p][nnB][qB + 4] = make_uint4(to_tf32(bpre[1].x), to_tf32(bpre[1].y),
                                                  to_tf32(bpre[1].z), to_tf32(bpre[1].w));
    };

    fetch(0);
    store(0);
    __syncthreads();

    for (int i = 0; i < NKIT; i++) {
        const int p = i & 1;
        if (i + 1 < NKIT) fetch((i + 1) * 16);

        #pragma unroll
        for (int ks = 0; ks < 2; ks++) {
            const int kb = ks * 8;
            uint32_t af[4][4], bf[4][2];
            #pragma unroll
            for (int im = 0; im < 4; im++) {
                int row = wm + im * 16 + lq;
                af[im][0] = As[p][kb + lr][row];
                af[im][1] = As[p][kb + lr][row + 8];
                af[im][2] = As[p][kb + lr + 4][row];
                af[im][3] = As[p][kb + lr + 4][row + 8];
            }
            #pragma unroll
            for (int in = 0; in < 4; in++) {
                int col = wn + in * 8 + lq;
                bf[in][0] = Bs[p][col][kb + lr];
                bf[in][1] = Bs[p][col][kb + lr + 4];
            }
            #pragma unroll
            for (int im = 0; im < 4; im++)
                #pragma unroll
                for (int in = 0; in < 4; in++)
                    mma_tf32(acc[im][in], af[im], bf[in]);
        }

        if (i + 1 < NKIT) {
            store(p ^ 1);
            __syncthreads();
        }
    }

    // epilogue
    #pragma unroll
    for (int im = 0; im < 4; im++) {
        const int r_lo = wm + im * 16 + lq;
        const int r_hi = r_lo + 8;
        #pragma unroll
        for (int in = 0; in < 4; in++) {
            const int col = n0 + wn + in * 8 + lr * 2;
            const float b0 = bias[col], b1 = bias[col + 1];
            if (MODE == 0) {
                *(float2*)(g_qkv + (size_t)(m0 + r_lo) * Nn + col) =
                    make_float2(acc[im][in][0] + b0, acc[im][in][1] + b1);
                *(float2*)(g_qkv + (size_t)(m0 + r_hi) * Nn + col) =
                    make_float2(acc[im][in][2] + b0, acc[im][in][3] + b1);
            } else {
                size_t o0 = ((size_t)(t * CC + col)) * SS + s0;
                size_t o1 = ((size_t)(t * CC + col + 1)) * SS + s0;
                Cout[o0 + r_lo] = acc[im][in][0] + b0 + x[o0 + r_lo];
                Cout[o1 + r_lo] = acc[im][in][1] + b1 + x[o1 + r_lo];
                Cout[o0 + r_hi] = acc[im][in][2] + b0 + x[o0 + r_hi];
                Cout[o1 + r_hi] = acc[im][in][3] + b1 + x[o1 + r_hi];
            }
        }
    }
}

// ---------------- 3) attention per (head, spatial) ----------------
__global__ __launch_bounds__(256)
void attn_kernel(const float* __restrict__ qs, const float* __restrict__ qb,
                 const float* __restrict__ ks, const float* __restrict__ kb,
                 const float* __restrict__ relb) {
    __shared__ float sq[16][193];
    __shared__ float attn[16][17];

    const int head = blockIdx.x;
    const int s    = blockIdx.y;
    const int tid  = threadIdx.x;

    for (int i = tid; i < 16 * 192; i += 256) {
        int tt = i / 192, c = i % 192;
        sq[tt][c] = g_qkv[((size_t)(tt * SS + s)) * NQKV + head * 192 + c];
    }
    __syncthreads();

    {
        int g   = tid >> 3;
        int l   = tid & 7;
        int row = g & 15;
        int off = (g < 16) ? 0 : 64;
        float sum = 0.f, ssq = 0.f;
        #pragma unroll
        for (int u = 0; u < 8; u++) {
            float v = sq[row][off + l + u * 8];
            sum += v; ssq += v * v;
        }
        #pragma unroll
        for (int m = 4; m; m >>= 1) {
            sum += __shfl_xor_sync(0xffffffffu, sum, m, 8);
            ssq += __shfl_xor_sync(0xffffffffu, ssq, m, 8);
        }
        float mu  = sum * (1.0f / 64.0f);
        float var = ssq * (1.0f / 64.0f) - mu * mu;
        float inv = rsqrtf(var + 1e-6f);
        const float* sc = (g < 16) ? qs : ks;
        const float* bi = (g < 16) ? qb : kb;
        #pragma unroll
        for (int u = 0; u < 8; u++) {
            int c = l + u * 8;
            sq[row][off + c] = (sq[row][off + c] - mu) * inv * sc[c] + bi[c];
        }
    }
    __syncthreads();

    {
        int i = tid >> 4, j = tid & 15;
        float dot = 0.f;
        #pragma unroll
        for (int c = 0; c < 64; c++) dot += sq[i][c] * sq[j][64 + c];

        int rp = j - i;
        int bucket = (rp > 0) ? 16 : 0;
        int n = abs(rp);
        if (n < 8) bucket += n;
        else {
            int large = 8 + (int)(__logf((float)n * 0.125f) * (8.0f / 2.7725887222397811f));
            bucket += (large < 15) ? large : 15;
        }
        float sc = dot * 0.125f + relb[bucket * NHEAD + head];

        float mx = sc;
        #pragma unroll
        for (int m = 8; m; m >>= 1) mx = fmaxf(mx, __shfl_xor_sync(0xffffffffu, mx, m, 16));
        float e = __expf(sc - mx);
        float sm = e;
        #pragma unroll
        for (int m = 8; m; m >>= 1) sm += __shfl_xor_sync(0xffffffffu, sm, m, 16);
        attn[i][j] = e / sm;
    }
    __syncthreads();

    #pragma unroll
    for (int l = 0; l < 4; l++) {
        int idx = tid + l * 256;
        int oi = idx >> 6, c = idx & 63;
        float acc = 0.f;
        #pragma unroll
        for (int tt = 0; tt < 16; tt++) acc += attn[oi][tt] * sq[tt][128 + c];
        g_att[((size_t)(oi * CC + head * HDIM + c)) * SS + s] = acc;
    }
}

extern "C" void kernel_launch(void* const* d_in, const int* in_sizes, int n_in,
                              void* d_out, int out_size) {
    const float* x    = (const float*)d_in[0];
    const float* w1   = (const float*)d_in[1];
    const float* Win  = (const float*)d_in[2];
    const float* binq = (const float*)d_in[3];
    const float* qsc  = (const float*)d_in[4];
    const float* qbi  = (const float*)d_in[5];
    const float* ksc  = (const float*)d_in[6];
    const float* kbi  = (const float*)d_in[7];
    const float* relb = (const float*)d_in[8];
    const float* Wout = (const float*)d_in[9];
    const float* bout = (const float*)d_in[10];
    float* out = (float*)d_out;

    rms_kernel<<<TT * NHEAD, 256>>>(x);
    mma_gemm<0><<<dim3(NQKV / 128, 256), 256>>>(x, Win, binq, w1, nullptr, NQKV);
    attn_kernel<<<dim3(NHEAD, SS), 256>>>(qsc, qbi, ksc, kbi, relb);
    mma_gemm<1><<<dim3(CC / 128, 256), 256>>>(x, Wout, bout, nullptr, out, CC);
}

// round 6
// speedup vs baseline: 2.3490x; 1.0561x over previous
#include <cuda_runtime.h>
#include <cstdint>

#define TT 16
#define CC 768
#define SS 2048
#define NHEAD 12
#define HDIM 64
#define NQKV 2304

// Scratch (device globals; no allocation allowed)
__device__ float g_invrms[TT * NHEAD];
__device__ float g_qkv[(size_t)32768 * NQKV];          // [m=t*2048+s][n]
__device__ float g_att[(size_t)TT * CC * SS];          // [t][c][s]

__device__ __forceinline__ uint32_t to_tf32(float x) {
    uint32_t o;
    asm("cvt.rna.tf32.f32 %0, %1;" : "=r"(o) : "f"(x));
    return o;
}

__device__ __forceinline__ void mma_tf32(float* d, const uint32_t* a, uint32_t b0, uint32_t b1) {
    asm volatile(
        "mma.sync.aligned.m16n8k8.row.col.f32.tf32.tf32.f32 "
        "{%0,%1,%2,%3}, {%4,%5,%6,%7}, {%8,%9}, {%0,%1,%2,%3};"
        : "+f"(d[0]), "+f"(d[1]), "+f"(d[2]), "+f"(d[3])
        : "r"(a[0]), "r"(a[1]), "r"(a[2]), "r"(a[3]), "r"(b0), "r"(b1));
}

__device__ __forceinline__ void cp16(uint32_t dst, const void* src) {
    asm volatile("cp.async.cg.shared.global [%0], [%1], 16;" :: "r"(dst), "l"(src));
}
#define CP_COMMIT() asm volatile("cp.async.commit_group;" ::: "memory")
#define CP_WAIT0()  asm volatile("cp.async.wait_group 0;" ::: "memory")

__device__ __forceinline__ void ldsm4(uint32_t* r, uint32_t addr) {
    asm volatile("ldmatrix.sync.aligned.m8n8.x4.shared.b16 {%0,%1,%2,%3}, [%4];"
        : "=r"(r[0]), "=r"(r[1]), "=r"(r[2]), "=r"(r[3]) : "r"(addr));
}

// ---------------- 1) group RMS ----------------
__global__ void rms_kernel(const float* __restrict__ x) {
    int b = blockIdx.x;
    const float4* p = (const float4*)(x + (size_t)b * 64 * SS);
    float s = 0.f;
    for (int i = threadIdx.x; i < (64 * SS) / 4; i += blockDim.x) {
        float4 v = p[i];
        s += v.x * v.x + v.y * v.y + v.z * v.z + v.w * v.w;
    }
    #pragma unroll
    for (int m = 16; m; m >>= 1) s += __shfl_xor_sync(0xffffffffu, s, m);
    __shared__ float red[8];
    if ((threadIdx.x & 31) == 0) red[threadIdx.x >> 5] = s;
    __syncthreads();
    if (threadIdx.x < 8) {
        s = red[threadIdx.x];
        #pragma unroll
        for (int m = 4; m; m >>= 1) s += __shfl_xor_sync(0xffu, s, m);
        if (threadIdx.x == 0)
            g_invrms[b] = rsqrtf(s * (1.0f / (64.0f * SS)) + 1e-6f);
    }
}

// ---------------- 2/4) mma.sync tf32 GEMM ----------------
// CTA 128x128, 8 warps (2x4), warp tile 64x32, K-chunk 16, 2-stage cp.async.
// A raw fp32 via cp.async (HW-truncated tf32). MODE 0 folds the rms scale into B.
// MODE 0: C -> g_qkv[m][n] (+bias).  MODE 1: B also cp.async; C -> out (+bias+residual).
#define NKIT 48
#define APAD 136
#define BPAD 20

template <int MODE>
__global__ __launch_bounds__(256, 2)
void mma_gemm(const float* __restrict__ x, const float* __restrict__ W,
              const float* __restrict__ bias, const float* __restrict__ w1,
              float* __restrict__ Cout, int Nn) {
    __shared__ uint32_t As[2][16][APAD];   // [buf][k][m]
    __shared__ uint32_t Bs[2][128][BPAD];  // [buf][n][k]

    const int tid  = threadIdx.x;
    const int wid  = tid >> 5;
    const int lane = tid & 31;
    const int wm   = (wid & 1) * 64;
    const int wn   = (wid >> 1) * 32;
    const int lq   = lane >> 2;
    const int lr   = lane & 3;

    const int m0 = blockIdx.y * 128;
    const int n0 = blockIdx.x * 128;
    const int t  = m0 >> 11;
    const int s0 = m0 & 2047;

    const float* Asrc = (MODE == 0) ? x : g_att;

    // A loader: rows kkA, kkA+8; m-chunk of 4 floats (16B)
    const int kkA = tid >> 5;
    const int mA  = (tid & 31) * 4;
    // B loader: row nnB, k-chunk qB..qB+7
    const int nnB = tid >> 1;
    const int qB  = (tid & 1) * 8;

    // ldmatrix lane address components for B fragments
    const int lrow = (lane & 7) + ((lane >> 4) << 3);   // 0..15
    const int lcol = ((lane >> 3) & 1) * 4;             // 0 or 4
    uint32_t bm[2][2];
    #pragma unroll
    for (int p = 0; p < 2; p++)
        #pragma unroll
        for (int ip = 0; ip < 2; ip++)
            bm[p][ip] = (uint32_t)__cvta_generic_to_shared(&Bs[p][wn + ip * 16 + lrow][lcol]);

    float acc[4][4][4];
    #pragma unroll
    for (int i = 0; i < 4; i++)
        #pragma unroll
        for (int j = 0; j < 4; j++)
            #pragma unroll
            for (int c = 0; c < 4; c++) acc[i][j][c] = 0.f;

    auto issueA = [&](int k0, int p) {
        #pragma unroll
        for (int r = 0; r < 2; r++) {
            int k = k0 + kkA + r * 8;
            cp16((uint32_t)__cvta_generic_to_shared(&As[p][kkA + r * 8][mA]),
                 Asrc + ((size_t)(t * CC + k)) * SS + s0 + mA);
        }
    };
    auto issueB = [&](int k0, int p) {   // MODE 1 only: raw copy
        const float* wp = W + (size_t)(n0 + nnB) * CC + k0 + qB;
        cp16((uint32_t)__cvta_generic_to_shared(&Bs[p][nnB][qB]), wp);
        cp16((uint32_t)__cvta_generic_to_shared(&Bs[p][nnB][qB + 4]), wp + 4);
    };

    float4 bpre0, bpre1;   // MODE 0 B staging
    int kpre = 0;
    auto ldgB = [&](int k0) {
        const float4* wp = (const float4*)(W + (size_t)(n0 + nnB) * CC + k0 + qB);
        bpre0 = wp[0];
        bpre1 = wp[1];
        kpre = k0 + qB;
    };
    auto stsB = [&](int p) {
        float s_ = g_invrms[t * NHEAD + (kpre >> 6)];
        const float4 wa = *(const float4*)(w1 + kpre);
        const float4 wb = *(const float4*)(w1 + kpre + 4);
        *(uint4*)&Bs[p][nnB][qB] = make_uint4(
            to_tf32(bpre0.x * s_ * wa.x), to_tf32(bpre0.y * s_ * wa.y),
            to_tf32(bpre0.z * s_ * wa.z), to_tf32(bpre0.w * s_ * wa.w));
        *(uint4*)&Bs[p][nnB][qB + 4] = make_uint4(
            to_tf32(bpre1.x * s_ * wb.x), to_tf32(bpre1.y * s_ * wb.y),
            to_tf32(bpre1.z * s_ * wb.z), to_tf32(bpre1.w * s_ * wb.w));
    };

    // prologue: stage 0
    issueA(0, 0);
    if (MODE == 1) issueB(0, 0);
    CP_COMMIT();
    if (MODE == 0) { ldgB(0); stsB(0); }

    for (int i = 0; i < NKIT; i++) {
        const int p = i & 1;
        CP_WAIT0();
        __syncthreads();

        if (i + 1 < NKIT) {
            issueA((i + 1) * 16, p ^ 1);
            if (MODE == 1) issueB((i + 1) * 16, p ^ 1);
            CP_COMMIT();
            if (MODE == 0) ldgB((i + 1) * 16);
        }

        #pragma unroll
        for (int ks = 0; ks < 2; ks++) {
            const int kb = ks * 8;
            uint32_t af[4][4], bfr[2][4];
            #pragma unroll
            for (int im = 0; im < 4; im++) {
                int row = wm + im * 16 + lq;
                af[im][0] = As[p][kb + lr][row];
                af[im][1] = As[p][kb + lr][row + 8];
                af[im][2] = As[p][kb + lr + 4][row];
                af[im][3] = As[p][kb + lr + 4][row + 8];
            }
            ldsm4(bfr[0], bm[p][0] + kb * 4);
            ldsm4(bfr[1], bm[p][1] + kb * 4);
            #pragma unroll
            for (int im = 0; im < 4; im++)
                #pragma unroll
                for (int in = 0; in < 4; in++)
                    mma_tf32(acc[im][in], af[im],
                             bfr[in >> 1][(in & 1) * 2], bfr[in >> 1][(in & 1) * 2 + 1]);
        }

        if (MODE == 0 && i + 1 < NKIT) stsB(p ^ 1);
    }

    // epilogue
    #pragma unroll
    for (int im = 0; im < 4; im++) {
        const int r_lo = wm + im * 16 + lq;
        const int r_hi = r_lo + 8;
        #pragma unroll
        for (int in = 0; in < 4; in++) {
            const int col = n0 + wn + in * 8 + lr * 2;
            const float b0 = bias[col], b1 = bias[col + 1];
            if (MODE == 0) {
                *(float2*)(g_qkv + (size_t)(m0 + r_lo) * Nn + col) =
                    make_float2(acc[im][in][0] + b0, acc[im][in][1] + b1);
                *(float2*)(g_qkv + (size_t)(m0 + r_hi) * Nn + col) =
                    make_float2(acc[im][in][2] + b0, acc[im][in][3] + b1);
            } else {
                size_t o0 = ((size_t)(t * CC + col)) * SS + s0;
                size_t o1 = ((size_t)(t * CC + col + 1)) * SS + s0;
                Cout[o0 + r_lo] = acc[im][in][0] + b0 + x[o0 + r_lo];
                Cout[o1 + r_lo] = acc[im][in][1] + b1 + x[o1 + r_lo];
                Cout[o0 + r_hi] = acc[im][in][2] + b0 + x[o0 + r_hi];
                Cout[o1 + r_hi] = acc[im][in][3] + b1 + x[o1 + r_hi];
            }
        }
    }
}

// ---------------- 3) attention: one block per (head, 8-s chunk) ----------------
__global__ __launch_bounds__(256)
void attn_kernel(const float* __restrict__ qs, const float* __restrict__ qb,
                 const float* __restrict__ ks, const float* __restrict__ kb,
                 const float* __restrict__ relb) {
    __shared__ float sq[16][193];      // [t][0:64)=q [64:128)=k [128:192)=v
    __shared__ float attnw[16][17];
    __shared__ float obuf[16][8][64];  // [t][s_local][c]

    const int head  = blockIdx.x;
    const int sbase = blockIdx.y * 8;
    const int tid   = threadIdx.x;

    for (int sl = 0; sl < 8; sl++) {
        const int s = sbase + sl;

        for (int i = tid; i < 16 * 192; i += 256) {
            int tt = i / 192, c = i % 192;
            sq[tt][c] = g_qkv[((size_t)(tt * SS + s)) * NQKV + head * 192 + c];
        }
        __syncthreads();

        {   // layernorm q (groups 0..15) / k (16..31), 8 lanes per row
            int g   = tid >> 3;
            int l   = tid & 7;
            int row = g & 15;
            int off = (g < 16) ? 0 : 64;
            float sum = 0.f, ssq = 0.f;
            #pragma unroll
            for (int u = 0; u < 8; u++) {
                float v = sq[row][off + l + u * 8];
                sum += v; ssq += v * v;
            }
            #pragma unroll
            for (int m = 4; m; m >>= 1) {
                sum += __shfl_xor_sync(0xffffffffu, sum, m, 8);
                ssq += __shfl_xor_sync(0xffffffffu, ssq, m, 8);
            }
            float mu  = sum * (1.0f / 64.0f);
            float var = ssq * (1.0f / 64.0f) - mu * mu;
            float inv = rsqrtf(var + 1e-6f);
            const float* sc = (g < 16) ? qs : ks;
            const float* bi = (g < 16) ? qb : kb;
            #pragma unroll
            for (int u = 0; u < 8; u++) {
                int c = l + u * 8;
                sq[row][off + c] = (sq[row][off + c] - mu) * inv * sc[c] + bi[c];
            }
        }
        __syncthreads();

        {   // scores + softmax
            int i = tid >> 4, j = tid & 15;
            float dot = 0.f;
            #pragma unroll
            for (int c = 0; c < 64; c++) dot += sq[i][c] * sq[j][64 + c];

            int rp = j - i;
            int bucket = (rp > 0) ? 16 : 0;
            int n = abs(rp);
            if (n < 8) bucket += n;
            else {
                int large = 8 + (int)(__logf((float)n * 0.125f) * (8.0f / 2.7725887222397811f));
                bucket += (large < 15) ? large : 15;
            }
            float sc = dot * 0.125f + relb[bucket * NHEAD + head];

            float mx = sc;
            #pragma unroll
            for (int m = 8; m; m >>= 1) mx = fmaxf(mx, __shfl_xor_sync(0xffffffffu, mx, m, 16));
            float e = __expf(sc - mx);
            float sm = e;
            #pragma unroll
            for (int m = 8; m; m >>= 1) sm += __shfl_xor_sync(0xffffffffu, sm, m, 16);
            attnw[i][j] = e / sm;
        }
        __syncthreads();

        #pragma unroll
        for (int l = 0; l < 4; l++) {
            int idx = tid + l * 256;
            int oi = idx >> 6, c = idx & 63;
            float a = 0.f;
            #pragma unroll
            for (int tt = 0; tt < 16; tt++) a += attnw[oi][tt] * sq[tt][128 + c];
            obuf[oi][sl][c] = a;
        }
        __syncthreads();
    }

    // bulk store: float4 runs along s
    for (int idx = tid; idx < 16 * 64 * 2; idx += 256) {
        int t_ = idx >> 7;
        int c  = (idx >> 1) & 63;
        int h  = idx & 1;
        float4 v;
        v.x = obuf[t_][h * 4 + 0][c];
        v.y = obuf[t_][h * 4 + 1][c];
        v.z = obuf[t_][h * 4 + 2][c];
        v.w = obuf[t_][h * 4 + 3][c];
        *(float4*)(g_att + ((size_t)(t_ * CC + head * 64 + c)) * SS + sbase + h * 4) = v;
    }
}

extern "C" void kernel_launch(void* const* d_in, const int* in_sizes, int n_in,
                              void* d_out, int out_size) {
    const float* x    = (const float*)d_in[0];
    const float* w1   = (const float*)d_in[1];
    const float* Win  = (const float*)d_in[2];
    const float* binq = (const float*)d_in[3];
    const float* qsc  = (const float*)d_in[4];
    const float* qbi  = (const float*)d_in[5];
    const float* ksc  = (const float*)d_in[6];
    const float* kbi  = (const float*)d_in[7];
    const float* relb = (const float*)d_in[8];
    const float* Wout = (const float*)d_in[9];
    const float* bout = (const float*)d_in[10];
    float* out = (float*)d_out;

    rms_kernel<<<TT * NHEAD, 256>>>(x);
    mma_gemm<0><<<dim3(NQKV / 128, 256), 256>>>(x, Win, binq, w1, nullptr, NQKV);
    attn_kernel<<<dim3(NHEAD, SS / 8), 256>>>(qsc, qbi, ksc, kbi, relb);
    mma_gemm<1><<<dim3(CC / 128, 256), 256>>>(x, Wout, bout, nullptr, out, CC);
}

// round 7
// speedup vs baseline: 2.4165x; 1.0288x over previous
#include <cuda_runtime.h>
#include <cstdint>

#define TT 16
#define CC 768
#define SS 2048
#define NHEAD 12
#define HDIM 64
#define NQKV 2304

// Scratch (device globals; no allocation allowed)
__device__ float g_invrms[TT * NHEAD];
__device__ float g_qkv[(size_t)32768 * NQKV];          // [m=t*2048+s][n]
__device__ float g_att[(size_t)TT * CC * SS];          // [t][c][s]

__device__ __forceinline__ uint32_t to_tf32(float x) {
    uint32_t o;
    asm("cvt.rna.tf32.f32 %0, %1;" : "=r"(o) : "f"(x));
    return o;
}

__device__ __forceinline__ void mma_tf32(float* d, const uint32_t* a, uint32_t b0, uint32_t b1) {
    asm volatile(
        "mma.sync.aligned.m16n8k8.row.col.f32.tf32.tf32.f32 "
        "{%0,%1,%2,%3}, {%4,%5,%6,%7}, {%8,%9}, {%0,%1,%2,%3};"
        : "+f"(d[0]), "+f"(d[1]), "+f"(d[2]), "+f"(d[3])
        : "r"(a[0]), "r"(a[1]), "r"(a[2]), "r"(a[3]), "r"(b0), "r"(b1));
}

__device__ __forceinline__ void cp16(uint32_t dst, const void* src) {
    asm volatile("cp.async.cg.shared.global [%0], [%1], 16;" :: "r"(dst), "l"(src));
}
#define CP_COMMIT() asm volatile("cp.async.commit_group;" ::: "memory")
#define CP_WAIT0()  asm volatile("cp.async.wait_group 0;" ::: "memory")
#define CP_WAIT1()  asm volatile("cp.async.wait_group 1;" ::: "memory")

__device__ __forceinline__ void ldsm4(uint32_t* r, uint32_t addr) {
    asm volatile("ldmatrix.sync.aligned.m8n8.x4.shared.b16 {%0,%1,%2,%3}, [%4];"
        : "=r"(r[0]), "=r"(r[1]), "=r"(r[2]), "=r"(r[3]) : "r"(addr));
}

// ---------------- 1) group RMS ----------------
__global__ void rms_kernel(const float* __restrict__ x) {
    int b = blockIdx.x;
    const float4* p = (const float4*)(x + (size_t)b * 64 * SS);
    float s = 0.f;
    for (int i = threadIdx.x; i < (64 * SS) / 4; i += blockDim.x) {
        float4 v = p[i];
        s += v.x * v.x + v.y * v.y + v.z * v.z + v.w * v.w;
    }
    #pragma unroll
    for (int m = 16; m; m >>= 1) s += __shfl_xor_sync(0xffffffffu, s, m);
    __shared__ float red[8];
    if ((threadIdx.x & 31) == 0) red[threadIdx.x >> 5] = s;
    __syncthreads();
    if (threadIdx.x < 8) {
        s = red[threadIdx.x];
        #pragma unroll
        for (int m = 4; m; m >>= 1) s += __shfl_xor_sync(0xffu, s, m);
        if (threadIdx.x == 0)
            g_invrms[b] = rsqrtf(s * (1.0f / (64.0f * SS)) + 1e-6f);
    }
}

// ---------------- 2/4) mma.sync tf32 GEMM, 3-stage cp.async ----------------
// CTA 128x128, 8 warps (2x4), warp tile 64x32, K-chunk 16.
// A raw fp32 via cp.async (HW-truncated tf32). MODE 0 folds rms scale into B.
#define NKIT 48
#define APAD 136
#define BPAD 20
#define A_WORDS (16 * APAD)            // per stage
#define B_WORDS (128 * BPAD)
#define SMEM_BYTES (3 * (A_WORDS + B_WORDS) * 4)

template <int MODE>
__global__ __launch_bounds__(256, 2)
void mma_gemm(const float* __restrict__ x, const float* __restrict__ W,
              const float* __restrict__ bias, const float* __restrict__ w1,
              float* __restrict__ Cout, int Nn) {
    extern __shared__ uint32_t smem[];
    uint32_t (*As)[16][APAD]  = (uint32_t (*)[16][APAD])smem;
    uint32_t (*Bs)[128][BPAD] = (uint32_t (*)[128][BPAD])(smem + 3 * A_WORDS);

    const int tid  = threadIdx.x;
    const int wid  = tid >> 5;
    const int lane = tid & 31;
    const int wm   = (wid & 1) * 64;
    const int wn   = (wid >> 1) * 32;
    const int lq   = lane >> 2;
    const int lr   = lane & 3;

    const int m0 = blockIdx.y * 128;
    const int n0 = blockIdx.x * 128;
    const int t  = m0 >> 11;
    const int s0 = m0 & 2047;

    const float* Asrc = (MODE == 0) ? x : g_att;

    const int kkA = tid >> 5;
    const int mA  = (tid & 31) * 4;
    const int nnB = tid >> 1;
    const int qB  = (tid & 1) * 8;

    const int lrow = (lane & 7) + ((lane >> 4) << 3);
    const int lcol = ((lane >> 3) & 1) * 4;
    uint32_t bm[3][2];
    #pragma unroll
    for (int p = 0; p < 3; p++)
        #pragma unroll
        for (int ip = 0; ip < 2; ip++)
            bm[p][ip] = (uint32_t)__cvta_generic_to_shared(&Bs[p][wn + ip * 16 + lrow][lcol]);

    float acc[4][4][4];
    #pragma unroll
    for (int i = 0; i < 4; i++)
        #pragma unroll
        for (int j = 0; j < 4; j++)
            #pragma unroll
            for (int c = 0; c < 4; c++) acc[i][j][c] = 0.f;

    auto issueA = [&](int k0, int p) {
        #pragma unroll
        for (int r = 0; r < 2; r++) {
            int k = k0 + kkA + r * 8;
            cp16((uint32_t)__cvta_generic_to_shared(&As[p][kkA + r * 8][mA]),
                 Asrc + ((size_t)(t * CC + k)) * SS + s0 + mA);
        }
    };
    auto issueB = [&](int k0, int p) {   // MODE 1: raw copy
        const float* wp = W + (size_t)(n0 + nnB) * CC + k0 + qB;
        cp16((uint32_t)__cvta_generic_to_shared(&Bs[p][nnB][qB]), wp);
        cp16((uint32_t)__cvta_generic_to_shared(&Bs[p][nnB][qB + 4]), wp + 4);
    };

    float4 bpre0, bpre1;   // MODE 0 staging
    int kpre = 0;
    auto ldgB = [&](int k0) {
        const float4* wp = (const float4*)(W + (size_t)(n0 + nnB) * CC + k0 + qB);
        bpre0 = wp[0];
        bpre1 = wp[1];
        kpre = k0 + qB;
    };
    auto stsB = [&](int p) {
        float s_ = g_invrms[t * NHEAD + (kpre >> 6)];
        const float4 wa = *(const float4*)(w1 + kpre);
        const float4 wb = *(const float4*)(w1 + kpre + 4);
        *(uint4*)&Bs[p][nnB][qB] = make_uint4(
            to_tf32(bpre0.x * s_ * wa.x), to_tf32(bpre0.y * s_ * wa.y),
            to_tf32(bpre0.z * s_ * wa.z), to_tf32(bpre0.w * s_ * wa.w));
        *(uint4*)&Bs[p][nnB][qB + 4] = make_uint4(
            to_tf32(bpre1.x * s_ * wb.x), to_tf32(bpre1.y * s_ * wb.y),
            to_tf32(bpre1.z * s_ * wb.z), to_tf32(bpre1.w * s_ * wb.w));
    };

    // prologue: stages 0 and 1 (one commit group each)
    issueA(0, 0);
    if (MODE == 1) issueB(0, 0);
    CP_COMMIT();
    issueA(16, 1);
    if (MODE == 1) issueB(16, 1);
    CP_COMMIT();
    if (MODE == 0) { ldgB(0); stsB(0); ldgB(16); stsB(1); }

    for (int i = 0; i < NKIT; i++) {
        const int p = i % 3;
        if (i >= NKIT - 2) { CP_WAIT0(); } else { CP_WAIT1(); }
        __syncthreads();

        if (i + 2 < NKIT) {
            const int pn = (i + 2) % 3;
            issueA((i + 2) * 16, pn);
            if (MODE == 1) issueB((i + 2) * 16, pn);
            CP_COMMIT();
            if (MODE == 0) ldgB((i + 2) * 16);
        }

        #pragma unroll
        for (int ks = 0; ks < 2; ks++) {
            const int kb = ks * 8;
            uint32_t af[4][4], bfr[2][4];
            #pragma unroll
            for (int im = 0; im < 4; im++) {
                int row = wm + im * 16 + lq;
                af[im][0] = As[p][kb + lr][row];
                af[im][1] = As[p][kb + lr][row + 8];
                af[im][2] = As[p][kb + lr + 4][row];
                af[im][3] = As[p][kb + lr + 4][row + 8];
            }
            ldsm4(bfr[0], bm[p][0] + kb * 4);
            ldsm4(bfr[1], bm[p][1] + kb * 4);
            #pragma unroll
            for (int im = 0; im < 4; im++)
                #pragma unroll
                for (int in = 0; in < 4; in++)
                    mma_tf32(acc[im][in], af[im],
                             bfr[in >> 1][(in & 1) * 2], bfr[in >> 1][(in & 1) * 2 + 1]);
        }

        if (MODE == 0 && i + 2 < NKIT) stsB((i + 2) % 3);
    }

    // epilogue
    #pragma unroll
    for (int im = 0; im < 4; im++) {
        const int r_lo = wm + im * 16 + lq;
        const int r_hi = r_lo + 8;
        #pragma unroll
        for (int in = 0; in < 4; in++) {
            const int col = n0 + wn + in * 8 + lr * 2;
            const float b0 = bias[col], b1 = bias[col + 1];
            if (MODE == 0) {
                *(float2*)(g_qkv + (size_t)(m0 + r_lo) * Nn + col) =
                    make_float2(acc[im][in][0] + b0, acc[im][in][1] + b1);
                *(float2*)(g_qkv + (size_t)(m0 + r_hi) * Nn + col) =
                    make_float2(acc[im][in][2] + b0, acc[im][in][3] + b1);
            } else {
                size_t o0 = ((size_t)(t * CC + col)) * SS + s0;
                size_t o1 = ((size_t)(t * CC + col + 1)) * SS + s0;
                Cout[o0 + r_lo] = acc[im][in][0] + b0 + x[o0 + r_lo];
                Cout[o1 + r_lo] = acc[im][in][1] + b1 + x[o1 + r_lo];
                Cout[o0 + r_hi] = acc[im][in][2] + b0 + x[o0 + r_hi];
                Cout[o1 + r_hi] = acc[im][in][3] + b1 + x[o1 + r_hi];
            }
        }
    }
}

// ---------------- 3) attention: one block per (head, 8-s chunk) ----------------
__global__ __launch_bounds__(256)
void attn_kernel(const float* __restrict__ qs, const float* __restrict__ qb,
                 const float* __restrict__ ks, const float* __restrict__ kb,
                 const float* __restrict__ relb) {
    __shared__ float sq[16][193];
    __shared__ float attnw[16][17];
    __shared__ float obuf[16][8][64];

    const int head  = blockIdx.x;
    const int sbase = blockIdx.y * 8;
    const int tid   = threadIdx.x;

    for (int sl = 0; sl < 8; sl++) {
        const int s = sbase + sl;

        for (int i = tid; i < 16 * 192; i += 256) {
            int tt = i / 192, c = i % 192;
            sq[tt][c] = g_qkv[((size_t)(tt * SS + s)) * NQKV + head * 192 + c];
        }
        __syncthreads();

        {
            int g   = tid >> 3;
            int l   = tid & 7;
            int row = g & 15;
            int off = (g < 16) ? 0 : 64;
            float sum = 0.f, ssq = 0.f;
            #pragma unroll
            for (int u = 0; u < 8; u++) {
                float v = sq[row][off + l + u * 8];
                sum += v; ssq += v * v;
            }
            #pragma unroll
            for (int m = 4; m; m >>= 1) {
                sum += __shfl_xor_sync(0xffffffffu, sum, m, 8);
                ssq += __shfl_xor_sync(0xffffffffu, ssq, m, 8);
            }
            float mu  = sum * (1.0f / 64.0f);
            float var = ssq * (1.0f / 64.0f) - mu * mu;
            float inv = rsqrtf(var + 1e-6f);
            const float* sc = (g < 16) ? qs : ks;
            const float* bi = (g < 16) ? qb : kb;
            #pragma unroll
            for (int u = 0; u < 8; u++) {
                int c = l + u * 8;
                sq[row][off + c] = (sq[row][off + c] - mu) * inv * sc[c] + bi[c];
            }
        }
        __syncthreads();

        {
            int i = tid >> 4, j = tid & 15;
            float dot = 0.f;
            #pragma unroll
            for (int c = 0; c < 64; c++) dot += sq[i][c] * sq[j][64 + c];

            int rp = j - i;
            int bucket = (rp > 0) ? 16 : 0;
            int n = abs(rp);
            if (n < 8) bucket += n;
            else {
                int large = 8 + (int)(__logf((float)n * 0.125f) * (8.0f / 2.7725887222397811f));
                bucket += (large < 15) ? large : 15;
            }
            float sc = dot * 0.125f + relb[bucket * NHEAD + head];

            float mx = sc;
            #pragma unroll
            for (int m = 8; m; m >>= 1) mx = fmaxf(mx, __shfl_xor_sync(0xffffffffu, mx, m, 16));
            float e = __expf(sc - mx);
            float sm = e;
            #pragma unroll
            for (int m = 8; m; m >>= 1) sm += __shfl_xor_sync(0xffffffffu, sm, m, 16);
            attnw[i][j] = e / sm;
        }
        __syncthreads();

        #pragma unroll
        for (int l = 0; l < 4; l++) {
            int idx = tid + l * 256;
            int oi = idx >> 6, c = idx & 63;
            float a = 0.f;
            #pragma unroll
            for (int tt = 0; tt < 16; tt++) a += attnw[oi][tt] * sq[tt][128 + c];
            obuf[oi][sl][c] = a;
        }
        __syncthreads();
    }

    for (int idx = tid; idx < 16 * 64 * 2; idx += 256) {
        int t_ = idx >> 7;
        int c  = (idx >> 1) & 63;
        int h  = idx & 1;
        float4 v;
        v.x = obuf[t_][h * 4 + 0][c];
        v.y = obuf[t_][h * 4 + 1][c];
        v.z = obuf[t_][h * 4 + 2][c];
        v.w = obuf[t_][h * 4 + 3][c];
        *(float4*)(g_att + ((size_t)(t_ * CC + head * 64 + c)) * SS + sbase + h * 4) = v;
    }
}

extern "C" void kernel_launch(void* const* d_in, const int* in_sizes, int n_in,
                              void* d_out, int out_size) {
    const float* x    = (const float*)d_in[0];
    const float* w1   = (const float*)d_in[1];
    const float* Win  = (const float*)d_in[2];
    const float* binq = (const float*)d_in[3];
    const float* qsc  = (const float*)d_in[4];
    const float* qbi  = (const float*)d_in[5];
    const float* ksc  = (const float*)d_in[6];
    const float* kbi  = (const float*)d_in[7];
    const float* relb = (const float*)d_in[8];
    const float* Wout = (const float*)d_in[9];
    const float* bout = (const float*)d_in[10];
    float* out = (float*)d_out;

    cudaFuncSetAttribute(mma_gemm<0>, cudaFuncAttributeMaxDynamicSharedMemorySize, SMEM_BYTES);
    cudaFuncSetAttribute(mma_gemm<1>, cudaFuncAttributeMaxDynamicSharedMemorySize, SMEM_BYTES);

    rms_kernel<<<TT * NHEAD, 256>>>(x);
    mma_gemm<0><<<dim3(NQKV / 128, 256), 256, SMEM_BYTES>>>(x, Win, binq, w1, nullptr, NQKV);
    attn_kernel<<<dim3(NHEAD, SS / 8), 256>>>(qsc, qbi, ksc, kbi, relb);
    mma_gemm<1><<<dim3(CC / 128, 256), 256, SMEM_BYTES>>>(x, Wout, bout, nullptr, out, CC);
}

// round 9
// speedup vs baseline: 2.7874x; 1.1535x over previous
#include <cuda_runtime.h>
#include <cuda_fp16.h>
#include <cstdint>

#define TT 16
#define CC 768
#define SS 2048
#define NHEAD 12
#define HDIM 64
#define NQKV 2304

// Scratch (device globals; no allocation allowed)
__device__ float  g_invrms[TT * NHEAD];
__device__ float  g_qkv[(size_t)32768 * NQKV];        // [m=t*2048+s][n] fp32
__device__ __half g_att_h[(size_t)TT * CC * SS];      // [t][c][s] fp16

__device__ __forceinline__ uint32_t packh(float lo, float hi) {
    __half2 h = __floats2half2_rn(lo, hi);
    return *(uint32_t*)&h;
}

__device__ __forceinline__ void mma_f16(float* d, const uint32_t* a, uint32_t b0, uint32_t b1) {
    asm volatile(
        "mma.sync.aligned.m16n8k16.row.col.f32.f16.f16.f32 "
        "{%0,%1,%2,%3}, {%4,%5,%6,%7}, {%8,%9}, {%0,%1,%2,%3};"
        : "+f"(d[0]), "+f"(d[1]), "+f"(d[2]), "+f"(d[3])
        : "r"(a[0]), "r"(a[1]), "r"(a[2]), "r"(a[3]), "r"(b0), "r"(b1));
}

__device__ __forceinline__ void cp16(uint32_t dst, const void* src) {
    asm volatile("cp.async.cg.shared.global [%0], [%1], 16;" :: "r"(dst), "l"(src));
}
#define CP_COMMIT() asm volatile("cp.async.commit_group;" ::: "memory")
#define CP_WAIT0()  asm volatile("cp.async.wait_group 0;" ::: "memory")

__device__ __forceinline__ void ldsm4(uint32_t* r, uint32_t addr) {
    asm volatile("ldmatrix.sync.aligned.m8n8.x4.shared.b16 {%0,%1,%2,%3}, [%4];"
        : "=r"(r[0]), "=r"(r[1]), "=r"(r[2]), "=r"(r[3]) : "r"(addr));
}
__device__ __forceinline__ void ldsm4t(uint32_t* r, uint32_t addr) {
    asm volatile("ldmatrix.sync.aligned.m8n8.x4.trans.shared.b16 {%0,%1,%2,%3}, [%4];"
        : "=r"(r[0]), "=r"(r[1]), "=r"(r[2]), "=r"(r[3]) : "r"(addr));
}

// ---------------- 1) group RMS ----------------
__global__ void rms_kernel(const float* __restrict__ x) {
    int b = blockIdx.x;
    const float4* p = (const float4*)(x + (size_t)b * 64 * SS);
    float s = 0.f;
    for (int i = threadIdx.x; i < (64 * SS) / 4; i += blockDim.x) {
        float4 v = p[i];
        s += v.x * v.x + v.y * v.y + v.z * v.z + v.w * v.w;
    }
    #pragma unroll
    for (int m = 16; m; m >>= 1) s += __shfl_xor_sync(0xffffffffu, s, m);
    __shared__ float red[8];
    if ((threadIdx.x & 31) == 0) red[threadIdx.x >> 5] = s;
    __syncthreads();
    if (threadIdx.x < 8) {
        s = red[threadIdx.x];
        #pragma unroll
        for (int m = 4; m; m >>= 1) s += __shfl_xor_sync(0xffu, s, m);
        if (threadIdx.x == 0)
            g_invrms[b] = rsqrtf(s * (1.0f / (64.0f * SS)) + 1e-6f);
    }
}

// ---------------- 2/4) mma.sync fp16 GEMM (m16n8k16) ----------------
// CTA 128x128, 8 warps (2x4), warp tile 64x32, K-chunk 32, double-buffered.
// As[k][m] fp16 (m-contig, pad 136 halves = 272B), frags via ldmatrix.trans.
// Bs[n][k] fp16 (k-contig, pad 40 halves = 80B, 16B-multiple!), frags via ldmatrix.
#define NKIT2 24
#define APADH 136
#define BPADH 40

template <int MODE>
__global__ __launch_bounds__(256, 2)
void mma_gemm(const float* __restrict__ x, const float* __restrict__ W,
              const float* __restrict__ bias, const float* __restrict__ w1,
              float* __restrict__ Cout, int Nn) {
    __shared__ __half As[2][32][APADH];
    __shared__ __half Bs[2][128][BPADH];

    const int tid  = threadIdx.x;
    const int wid  = tid >> 5;
    const int lane = tid & 31;
    const int wm   = (wid & 1) * 64;
    const int wn   = (wid >> 1) * 32;
    const int lq   = lane >> 2;
    const int lr   = lane & 3;

    const int m0 = blockIdx.y * 128;
    const int n0 = blockIdx.x * 128;
    const int t  = m0 >> 11;
    const int s0 = m0 & 2047;

    // ldmatrix lane addresses
    const int kA_l = ((lane >> 4) << 3) + (lane & 7);       // 0..15
    const int mOff = (((lane >> 3) & 1) << 3);              // 0/8
    const int nB_l = (((lane >> 3) & 1) << 3) + (lane & 7); // 0..15
    const int kB_l = ((lane >> 4) << 3);                    // 0/8
    uint32_t aA[2][4], aB[2][2];
    #pragma unroll
    for (int p = 0; p < 2; p++) {
        #pragma unroll
        for (int im = 0; im < 4; im++)
            aA[p][im] = (uint32_t)__cvta_generic_to_shared(&As[p][kA_l][wm + im * 16 + mOff]);
        #pragma unroll
        for (int bg = 0; bg < 2; bg++)
            aB[p][bg] = (uint32_t)__cvta_generic_to_shared(&Bs[p][wn + bg * 16 + nB_l][kB_l]);
    }

    // loader indices
    const int kA = tid >> 3;          // 0..31
    const int cA = (tid & 7) * 16;    // m chunk
    const int nB = tid >> 1;          // 0..127
    const int hB = (tid & 1) * 16;    // k chunk

    float acc[4][4][4];
    #pragma unroll
    for (int i = 0; i < 4; i++)
        #pragma unroll
        for (int j = 0; j < 4; j++)
            #pragma unroll
            for (int c = 0; c < 4; c++) acc[i][j][c] = 0.f;

    uint32_t awr[8], bwr[8];

    auto ldgA = [&](int k0) {          // MODE 0: x fp32 -> packed f16
        const float* src = x + ((size_t)(t * CC + k0 + kA)) * SS + s0 + cA;
        #pragma unroll
        for (int q = 0; q < 4; q++) {
            float4 v = *(const float4*)(src + q * 4);
            awr[2 * q]     = packh(v.x, v.y);
            awr[2 * q + 1] = packh(v.z, v.w);
        }
    };
    auto stsA = [&](int p) {
        *(uint4*)&As[p][kA][cA]     = *(uint4*)&awr[0];
        *(uint4*)&As[p][kA][cA + 8] = *(uint4*)&awr[4];
    };
    auto issueA = [&](int k0, int p) { // MODE 1: g_att_h via cp.async
        #pragma unroll
        for (int r = 0; r < 2; r++) {
            int o = tid * 2 + r;
            int row = o >> 4;
            int ch  = (o & 15) * 8;
            cp16((uint32_t)__cvta_generic_to_shared(&As[p][row][ch]),
                 g_att_h + ((size_t)(t * CC + k0 + row)) * SS + s0 + ch);
        }
    };
    auto ldgB = [&](int k0) {
        const float* wp = W + (size_t)(n0 + nB) * CC + k0 + hB;
        if (MODE == 0) {
            float s_ = g_invrms[t * NHEAD + ((k0 + hB) >> 6)];
            #pragma unroll
            for (int q = 0; q < 4; q++) {
                float4 v  = *(const float4*)(wp + q * 4);
                float4 wv = *(const float4*)(w1 + k0 + hB + q * 4);
                bwr[2 * q]     = packh(v.x * s_ * wv.x, v.y * s_ * wv.y);
                bwr[2 * q + 1] = packh(v.z * s_ * wv.z, v.w * s_ * wv.w);
            }
        } else {
            #pragma unroll
            for (int q = 0; q < 4; q++) {
                float4 v = *(const float4*)(wp + q * 4);
                bwr[2 * q]     = packh(v.x, v.y);
                bwr[2 * q + 1] = packh(v.z, v.w);
            }
        }
    };
    auto stsB = [&](int p) {
        *(uint4*)&Bs[p][nB][hB]     = *(uint4*)&bwr[0];
        *(uint4*)&Bs[p][nB][hB + 8] = *(uint4*)&bwr[4];
    };

    // prologue
    if (MODE == 0) { ldgA(0); stsA(0); }
    else           { issueA(0, 0); CP_COMMIT(); }
    ldgB(0); stsB(0);
    if (MODE == 1) CP_WAIT0();
    __syncthreads();

    for (int i = 0; i < NKIT2; i++) {
        const int p = i & 1;
        if (i + 1 < NKIT2) {
            if (MODE == 0) ldgA((i + 1) * 32);
            else { issueA((i + 1) * 32, p ^ 1); CP_COMMIT(); }
            ldgB((i + 1) * 32);
        }

        #pragma unroll
        for (int ks = 0; ks < 2; ks++) {
            uint32_t af[4][4], bf[2][4];
            #pragma unroll
            for (int im = 0; im < 4; im++) ldsm4t(af[im], aA[p][im] + ks * (16 * APADH * 2));
            #pragma unroll
            for (int bg = 0; bg < 2; bg++) ldsm4(bf[bg], aB[p][bg] + ks * 32);
            #pragma unroll
            for (int im = 0; im < 4; im++)
                #pragma unroll
                for (int in = 0; in < 4; in++)
                    mma_f16(acc[im][in], af[im], bf[in >> 1][in & 1], bf[in >> 1][(in & 1) + 2]);
        }

        if (i + 1 < NKIT2) {
            if (MODE == 0) stsA(p ^ 1);
            stsB(p ^ 1);
            if (MODE == 1) CP_WAIT0();
        }
        __syncthreads();
    }

    // epilogue
    #pragma unroll
    for (int im = 0; im < 4; im++) {
        const int r_lo = wm + im * 16 + lq;
        const int r_hi = r_lo + 8;
        #pragma unroll
        for (int in = 0; in < 4; in++) {
            const int col = n0 + wn + in * 8 + lr * 2;
            const float b0 = bias[col], b1 = bias[col + 1];
            if (MODE == 0) {
                *(float2*)(g_qkv + (size_t)(m0 + r_lo) * Nn + col) =
                    make_float2(acc[im][in][0] + b0, acc[im][in][1] + b1);
                *(float2*)(g_qkv + (size_t)(m0 + r_hi) * Nn + col) =
                    make_float2(acc[im][in][2] + b0, acc[im][in][3] + b1);
            } else {
                size_t o0 = ((size_t)(t * CC + col)) * SS + s0;
                size_t o1 = ((size_t)(t * CC + col + 1)) * SS + s0;
                Cout[o0 + r_lo] = acc[im][in][0] + b0 + x[o0 + r_lo];
                Cout[o1 + r_lo] = acc[im][in][1] + b1 + x[o1 + r_lo];
                Cout[o0 + r_hi] = acc[im][in][2] + b0 + x[o0 + r_hi];
                Cout[o1 + r_hi] = acc[im][in][3] + b1 + x[o1 + r_hi];
            }
        }
    }
}

// ---------------- 3) attention: one block per (head, 8-s chunk) ----------------
__global__ __launch_bounds__(256)
void attn_kernel(const float* __restrict__ qs, const float* __restrict__ qb,
                 const float* __restrict__ ks, const float* __restrict__ kb,
                 const float* __restrict__ relb) {
    __shared__ float sq[16][193];
    __shared__ float attnw[16][17];
    __shared__ float obuf[16][8][64];

    const int head  = blockIdx.x;
    const int sbase = blockIdx.y * 8;
    const int tid   = threadIdx.x;

    for (int sl = 0; sl < 8; sl++) {
        const int s = sbase + sl;

        for (int i = tid; i < 16 * 192; i += 256) {
            int tt = i / 192, c = i % 192;
            sq[tt][c] = g_qkv[((size_t)(tt * SS + s)) * NQKV + head * 192 + c];
        }
        __syncthreads();

        {
            int g   = tid >> 3;
            int l   = tid & 7;
            int row = g & 15;
            int off = (g < 16) ? 0 : 64;
            float sum = 0.f, ssq = 0.f;
            #pragma unroll
            for (int u = 0; u < 8; u++) {
                float v = sq[row][off + l + u * 8];
                sum += v; ssq += v * v;
            }
            #pragma unroll
            for (int m = 4; m; m >>= 1) {
                sum += __shfl_xor_sync(0xffffffffu, sum, m, 8);
                ssq += __shfl_xor_sync(0xffffffffu, ssq, m, 8);
            }
            float mu  = sum * (1.0f / 64.0f);
            float var = ssq * (1.0f / 64.0f) - mu * mu;
            float inv = rsqrtf(var + 1e-6f);
            const float* sc = (g < 16) ? qs : ks;
            const float* bi = (g < 16) ? qb : kb;
            #pragma unroll
            for (int u = 0; u < 8; u++) {
                int c = l + u * 8;
                sq[row][off + c] = (sq[row][off + c] - mu) * inv * sc[c] + bi[c];
            }
        }
        __syncthreads();

        {
            int i = tid >> 4, j = tid & 15;
            float dot = 0.f;
            #pragma unroll
            for (int c = 0; c < 64; c++) dot += sq[i][c] * sq[j][64 + c];

            int rp = j - i;
            int bucket = (rp > 0) ? 16 : 0;
            int n = abs(rp);
            if (n < 8) bucket += n;
            else {
                int large = 8 + (int)(__logf((float)n * 0.125f) * (8.0f / 2.7725887222397811f));
                bucket += (large < 15) ? large : 15;
            }
            float sc = dot * 0.125f + relb[bucket * NHEAD + head];

            float mx = sc;
            #pragma unroll
            for (int m = 8; m; m >>= 1) mx = fmaxf(mx, __shfl_xor_sync(0xffffffffu, mx, m, 16));
            float e = __expf(sc - mx);
            float sm = e;
            #pragma unroll
            for (int m = 8; m; m >>= 1) sm += __shfl_xor_sync(0xffffffffu, sm, m, 16);
            attnw[i][j] = e / sm;
        }
        __syncthreads();

        #pragma unroll
        for (int l = 0; l < 4; l++) {
            int idx = tid + l * 256;
            int oi = idx >> 6, c = idx & 63;
            float a = 0.f;
            #pragma unroll
            for (int tt = 0; tt < 16; tt++) a += attnw[oi][tt] * sq[tt][128 + c];
            obuf[oi][sl][c] = a;
        }
        __syncthreads();
    }

    // fp16 writeback: 8 s-consecutive halves per (t,c) = one 16B store
    for (int idx = tid; idx < 16 * 64; idx += 256) {
        int t_ = idx >> 6;
        int c  = idx & 63;
        __half h[8];
        #pragma unroll
        for (int j = 0; j < 8; j++) h[j] = __float2half(obuf[t_][j][c]);
        *(uint4*)(g_att_h + ((size_t)(t_ * CC + head * 64 + c)) * SS + sbase) = *(uint4*)h;
    }
}

extern "C" void kernel_launch(void* const* d_in, const int* in_sizes, int n_in,
                              void* d_out, int out_size) {
    const float* x    = (const float*)d_in[0];
    const float* w1   = (const float*)d_in[1];
    const float* Win  = (const float*)d_in[2];
    const float* binq = (const float*)d_in[3];
    const float* qsc  = (const float*)d_in[4];
    const float* qbi  = (const float*)d_in[5];
    const float* ksc  = (const float*)d_in[6];
    const float* kbi  = (const float*)d_in[7];
    const float* relb = (const float*)d_in[8];
    const float* Wout = (const float*)d_in[9];
    const float* bout = (const float*)d_in[10];
    float* out = (float*)d_out;

    rms_kernel<<<TT * NHEAD, 256>>>(x);
    mma_gemm<0><<<dim3(NQKV / 128, 256), 256>>>(x, Win, binq, w1, nullptr, NQKV);
    attn_kernel<<<dim3(NHEAD, SS / 8), 256>>>(qsc, qbi, ksc, kbi, relb);
    mma_gemm<1><<<dim3(CC / 128, 256), 256>>>(x, Wout, bout, nullptr, out, CC);
}

// round 10
// speedup vs baseline: 3.9557x; 1.4191x over previous
#include <cuda_runtime.h>
#include <cuda_fp16.h>
#include <cstdint>

#define TT 16
#define CC 768
#define SS 2048
#define NHEAD 12
#define HDIM 64
#define NQKV 2304

// Scratch (device globals; no allocation allowed)
__device__ float  g_invrms[TT * NHEAD];
__device__ __half g_xh[(size_t)TT * CC * SS];          // fp16(x * invrms * w1), [t][k][s]
__device__ __half g_wh_in[(size_t)NQKV * CC];          // fp16(Win)
__device__ __half g_wh_out[(size_t)CC * CC];           // fp16(Wout)
__device__ __half g_qkv_h[(size_t)32768 * NQKV];       // [m=t*2048+s][n] fp16
__device__ __half g_att_h[(size_t)TT * CC * SS];       // [t][c][s] fp16

__device__ __forceinline__ uint32_t packh(float lo, float hi) {
    __half2 h = __floats2half2_rn(lo, hi);
    return *(uint32_t*)&h;
}

__device__ __forceinline__ void mma_f16(float* d, const uint32_t* a, uint32_t b0, uint32_t b1) {
    asm volatile(
        "mma.sync.aligned.m16n8k16.row.col.f32.f16.f16.f32 "
        "{%0,%1,%2,%3}, {%4,%5,%6,%7}, {%8,%9}, {%0,%1,%2,%3};"
        : "+f"(d[0]), "+f"(d[1]), "+f"(d[2]), "+f"(d[3])
        : "r"(a[0]), "r"(a[1]), "r"(a[2]), "r"(a[3]), "r"(b0), "r"(b1));
}

__device__ __forceinline__ void cp16(uint32_t dst, const void* src) {
    asm volatile("cp.async.cg.shared.global [%0], [%1], 16;" :: "r"(dst), "l"(src));
}
#define CP_COMMIT() asm volatile("cp.async.commit_group;" ::: "memory")
#define CP_WAIT0()  asm volatile("cp.async.wait_group 0;" ::: "memory")

__device__ __forceinline__ void ldsm4(uint32_t* r, uint32_t addr) {
    asm volatile("ldmatrix.sync.aligned.m8n8.x4.shared.b16 {%0,%1,%2,%3}, [%4];"
        : "=r"(r[0]), "=r"(r[1]), "=r"(r[2]), "=r"(r[3]) : "r"(addr));
}
__device__ __forceinline__ void ldsm4t(uint32_t* r, uint32_t addr) {
    asm volatile("ldmatrix.sync.aligned.m8n8.x4.trans.shared.b16 {%0,%1,%2,%3}, [%4];"
        : "=r"(r[0]), "=r"(r[1]), "=r"(r[2]), "=r"(r[3]) : "r"(addr));
}

// ---------------- 1) group RMS ----------------
__global__ void rms_kernel(const float* __restrict__ x) {
    int b = blockIdx.x;
    const float4* p = (const float4*)(x + (size_t)b * 64 * SS);
    float s = 0.f;
    for (int i = threadIdx.x; i < (64 * SS) / 4; i += blockDim.x) {
        float4 v = p[i];
        s += v.x * v.x + v.y * v.y + v.z * v.z + v.w * v.w;
    }
    #pragma unroll
    for (int m = 16; m; m >>= 1) s += __shfl_xor_sync(0xffffffffu, s, m);
    __shared__ float red[8];
    if ((threadIdx.x & 31) == 0) red[threadIdx.x >> 5] = s;
    __syncthreads();
    if (threadIdx.x < 8) {
        s = red[threadIdx.x];
        #pragma unroll
        for (int m = 4; m; m >>= 1) s += __shfl_xor_sync(0xffu, s, m);
        if (threadIdx.x == 0)
            g_invrms[b] = rsqrtf(s * (1.0f / (64.0f * SS)) + 1e-6f);
    }
}

// ---------------- 1b) prep: xh = fp16(x * invrms * w1) ----------------
__global__ __launch_bounds__(256)
void convx_kernel(const float* __restrict__ x, const float* __restrict__ w1) {
    int row = blockIdx.x;                 // t*CC + k
    int t = row / CC, k = row - t * CC;
    float sc = g_invrms[t * NHEAD + (k >> 6)] * w1[k];
    const float4* src = (const float4*)(x + (size_t)row * SS);
    __half* dst = g_xh + (size_t)row * SS;
    int i = threadIdx.x;                  // SS/8 = 256 chunks
    float4 a = src[2 * i], b = src[2 * i + 1];
    uint32_t o[4] = {packh(a.x * sc, a.y * sc), packh(a.z * sc, a.w * sc),
                     packh(b.x * sc, b.y * sc), packh(b.z * sc, b.w * sc)};
    *(uint4*)(dst + i * 8) = *(uint4*)o;
}

// ---------------- 1c) prep: fp16 weight copies ----------------
__global__ __launch_bounds__(256)
void convw_kernel(const float* __restrict__ src, __half* __restrict__ dst, int n4) {
    int i = blockIdx.x * blockDim.x + threadIdx.x;
    if (i < n4) {
        float4 v = ((const float4*)src)[i];
        uint32_t o[2] = {packh(v.x, v.y), packh(v.z, v.w)};
        *(uint2*)(dst + (size_t)i * 4) = *(uint2*)o;
    }
}

// ---------------- 2/4) mma.sync fp16 GEMM (m16n8k16), pure cp.async ----------------
// CTA 128x128, 8 warps (2x4), warp tile 64x32, K-chunk 32, double-buffered.
// As[k][m] (m-contig, pad 136h = 272B), frags via ldmatrix.trans.
// Bs[n][k] (k-contig, pad 40h = 80B), frags via ldmatrix.
// MODE 0: A=g_xh, B=g_wh_in  -> g_qkv_h (fp16, +bias)
// MODE 1: A=g_att_h, B=g_wh_out -> Cout fp32 (+bias+residual)
#define NKIT2 24
#define APADH 136
#define BPADH 40

template <int MODE>
__global__ __launch_bounds__(256, 2)
void mma_gemm(const float* __restrict__ x, const float* __restrict__ bias,
              float* __restrict__ Cout, int Nn) {
    __shared__ __half As[2][32][APADH];
    __shared__ __half Bs[2][128][BPADH];

    const int tid  = threadIdx.x;
    const int wid  = tid >> 5;
    const int lane = tid & 31;
    const int wm   = (wid & 1) * 64;
    const int wn   = (wid >> 1) * 32;
    const int lq   = lane >> 2;
    const int lr   = lane & 3;

    const int m0 = blockIdx.y * 128;
    const int n0 = blockIdx.x * 128;
    const int t  = m0 >> 11;
    const int s0 = m0 & 2047;

    const __half* Asrc = (MODE == 0) ? g_xh : g_att_h;
    const __half* Bsrc = (MODE == 0) ? g_wh_in : g_wh_out;

    // ldmatrix lane addresses
    const int kA_l = ((lane >> 4) << 3) + (lane & 7);
    const int mOff = (((lane >> 3) & 1) << 3);
    const int nB_l = (((lane >> 3) & 1) << 3) + (lane & 7);
    const int kB_l = ((lane >> 4) << 3);
    uint32_t aA[2][4], aB[2][2];
    #pragma unroll
    for (int p = 0; p < 2; p++) {
        #pragma unroll
        for (int im = 0; im < 4; im++)
            aA[p][im] = (uint32_t)__cvta_generic_to_shared(&As[p][kA_l][wm + im * 16 + mOff]);
        #pragma unroll
        for (int bg = 0; bg < 2; bg++)
            aB[p][bg] = (uint32_t)__cvta_generic_to_shared(&Bs[p][wn + bg * 16 + nB_l][kB_l]);
    }

    float acc[4][4][4];
    #pragma unroll
    for (int i = 0; i < 4; i++)
        #pragma unroll
        for (int j = 0; j < 4; j++)
            #pragma unroll
            for (int c = 0; c < 4; c++) acc[i][j][c] = 0.f;

    auto issueA = [&](int k0, int p) {
        #pragma unroll
        for (int r = 0; r < 2; r++) {
            int o = tid * 2 + r;
            int row = o >> 4;
            int ch  = (o & 15) * 8;
            cp16((uint32_t)__cvta_generic_to_shared(&As[p][row][ch]),
                 Asrc + ((size_t)(t * CC + k0 + row)) * SS + s0 + ch);
        }
    };
    auto issueB = [&](int k0, int p) {
        #pragma unroll
        for (int r = 0; r < 2; r++) {
            int o = tid * 2 + r;
            int row = o >> 2;
            int ch  = (o & 3) * 8;
            cp16((uint32_t)__cvta_generic_to_shared(&Bs[p][row][ch]),
                 Bsrc + (size_t)(n0 + row) * CC + k0 + ch);
        }
    };

    issueA(0, 0);
    issueB(0, 0);
    CP_COMMIT();

    for (int i = 0; i < NKIT2; i++) {
        const int p = i & 1;
        CP_WAIT0();
        __syncthreads();
        if (i + 1 < NKIT2) {
            issueA((i + 1) * 32, p ^ 1);
            issueB((i + 1) * 32, p ^ 1);
            CP_COMMIT();
        }

        #pragma unroll
        for (int ks = 0; ks < 2; ks++) {
            uint32_t af[4][4], bf[2][4];
            #pragma unroll
            for (int im = 0; im < 4; im++) ldsm4t(af[im], aA[p][im] + ks * (16 * APADH * 2));
            #pragma unroll
            for (int bg = 0; bg < 2; bg++) ldsm4(bf[bg], aB[p][bg] + ks * 32);
            #pragma unroll
            for (int im = 0; im < 4; im++)
                #pragma unroll
                for (int in = 0; in < 4; in++)
                    mma_f16(acc[im][in], af[im], bf[in >> 1][in & 1], bf[in >> 1][(in & 1) + 2]);
        }
    }

    // epilogue
    #pragma unroll
    for (int im = 0; im < 4; im++) {
        const int r_lo = wm + im * 16 + lq;
        const int r_hi = r_lo + 8;
        #pragma unroll
        for (int in = 0; in < 4; in++) {
            const int col = n0 + wn + in * 8 + lr * 2;
            const float b0 = bias[col], b1 = bias[col + 1];
            if (MODE == 0) {
                __half2 vlo = __floats2half2_rn(acc[im][in][0] + b0, acc[im][in][1] + b1);
                __half2 vhi = __floats2half2_rn(acc[im][in][2] + b0, acc[im][in][3] + b1);
                *(__half2*)(g_qkv_h + (size_t)(m0 + r_lo) * Nn + col) = vlo;
                *(__half2*)(g_qkv_h + (size_t)(m0 + r_hi) * Nn + col) = vhi;
            } else {
                size_t o0 = ((size_t)(t * CC + col)) * SS + s0;
                size_t o1 = ((size_t)(t * CC + col + 1)) * SS + s0;
                Cout[o0 + r_lo] = acc[im][in][0] + b0 + x[o0 + r_lo];
                Cout[o1 + r_lo] = acc[im][in][1] + b1 + x[o1 + r_lo];
                Cout[o0 + r_hi] = acc[im][in][2] + b0 + x[o0 + r_hi];
                Cout[o1 + r_hi] = acc[im][in][3] + b1 + x[o1 + r_hi];
            }
        }
    }
}

// ---------------- 3) attention: one block per (head, 8-s chunk) ----------------
__global__ __launch_bounds__(256)
void attn_kernel(const float* __restrict__ qs, const float* __restrict__ qb,
                 const float* __restrict__ ks, const float* __restrict__ kb,
                 const float* __restrict__ relb) {
    __shared__ float sq[16][193];
    __shared__ float attnw[16][17];
    __shared__ float obuf[16][8][64];

    const int head  = blockIdx.x;
    const int sbase = blockIdx.y * 8;
    const int tid   = threadIdx.x;

    for (int sl = 0; sl < 8; sl++) {
        const int s = sbase + sl;

        for (int i = tid; i < 16 * 192; i += 256) {
            int tt = i / 192, c = i % 192;
            sq[tt][c] = __half2float(g_qkv_h[((size_t)(tt * SS + s)) * NQKV + head * 192 + c]);
        }
        __syncthreads();

        {
            int g   = tid >> 3;
            int l   = tid & 7;
            int row = g & 15;
            int off = (g < 16) ? 0 : 64;
            float sum = 0.f, ssq = 0.f;
            #pragma unroll
            for (int u = 0; u < 8; u++) {
                float v = sq[row][off + l + u * 8];
                sum += v; ssq += v * v;
            }
            #pragma unroll
            for (int m = 4; m; m >>= 1) {
                sum += __shfl_xor_sync(0xffffffffu, sum, m, 8);
                ssq += __shfl_xor_sync(0xffffffffu, ssq, m, 8);
            }
            float mu  = sum * (1.0f / 64.0f);
            float var = ssq * (1.0f / 64.0f) - mu * mu;
            float inv = rsqrtf(var + 1e-6f);
            const float* sc = (g < 16) ? qs : ks;
            const float* bi = (g < 16) ? qb : kb;
            #pragma unroll
            for (int u = 0; u < 8; u++) {
                int c = l + u * 8;
                sq[row][off + c] = (sq[row][off + c] - mu) * inv * sc[c] + bi[c];
            }
        }
        __syncthreads();

        {
            int i = tid >> 4, j = tid & 15;
            float dot = 0.f;
            #pragma unroll
            for (int c = 0; c < 64; c++) dot += sq[i][c] * sq[j][64 + c];

            int rp = j - i;
            int bucket = (rp > 0) ? 16 : 0;
            int n = abs(rp);
            if (n < 8) bucket += n;
            else {
                int large = 8 + (int)(__logf((float)n * 0.125f) * (8.0f / 2.7725887222397811f));
                bucket += (large < 15) ? large : 15;
            }
            float sc = dot * 0.125f + relb[bucket * NHEAD + head];

            float mx = sc;
            #pragma unroll
            for (int m = 8; m; m >>= 1) mx = fmaxf(mx, __shfl_xor_sync(0xffffffffu, mx, m, 16));
            float e = __expf(sc - mx);
            float sm = e;
            #pragma unroll
            for (int m = 8; m; m >>= 1) sm += __shfl_xor_sync(0xffffffffu, sm, m, 16);
            attnw[i][j] = e / sm;
        }
        __syncthreads();

        #pragma unroll
        for (int l = 0; l < 4; l++) {
            int idx = tid + l * 256;
            int oi = idx >> 6, c = idx & 63;
            float a = 0.f;
            #pragma unroll
            for (int tt = 0; tt < 16; tt++) a += attnw[oi][tt] * sq[tt][128 + c];
            obuf[oi][sl][c] = a;
        }
        __syncthreads();
    }

    for (int idx = tid; idx < 16 * 64; idx += 256) {
        int t_ = idx >> 6;
        int c  = idx & 63;
        __half h[8];
        #pragma unroll
        for (int j = 0; j < 8; j++) h[j] = __float2half(obuf[t_][j][c]);
        *(uint4*)(g_att_h + ((size_t)(t_ * CC + head * 64 + c)) * SS + sbase) = *(uint4*)h;
    }
}

extern "C" void kernel_launch(void* const* d_in, const int* in_sizes, int n_in,
                              void* d_out, int out_size) {
    const float* x    = (const float*)d_in[0];
    const float* w1   = (const float*)d_in[1];
    const float* Win  = (const float*)d_in[2];
    const float* binq = (const float*)d_in[3];
    const float* qsc  = (const float*)d_in[4];
    const float* qbi  = (const float*)d_in[5];
    const float* ksc  = (const float*)d_in[6];
    const float* kbi  = (const float*)d_in[7];
    const float* relb = (const float*)d_in[8];
    const float* Wout = (const float*)d_in[9];
    const float* bout = (const float*)d_in[10];
    float* out = (float*)d_out;

    __half *wh_in_p, *wh_out_p;
    cudaGetSymbolAddress((void**)&wh_in_p, g_wh_in);
    cudaGetSymbolAddress((void**)&wh_out_p, g_wh_out);

    rms_kernel<<<TT * NHEAD, 256>>>(x);
    convx_kernel<<<TT * CC, 256>>>(x, w1);
    convw_kernel<<<(NQKV * CC / 4 + 255) / 256, 256>>>(Win, wh_in_p, NQKV * CC / 4);
    convw_kernel<<<(CC * CC / 4 + 255) / 256, 256>>>(Wout, wh_out_p, CC * CC / 4);
    mma_gemm<0><<<dim3(NQKV / 128, 256), 256>>>(x, binq, nullptr, NQKV);
    attn_kernel<<<dim3(NHEAD, SS / 8), 256>>>(qsc, qbi, ksc, kbi, relb);
    mma_gemm<1><<<dim3(CC / 128, 256), 256>>>(x, bout, out, CC);
}

// round 11
// speedup vs baseline: 4.1727x; 1.0549x over previous
#include <cuda_runtime.h>
#include <cuda_fp16.h>
#include <cstdint>

#define TT 16
#define CC 768
#define SS 2048
#define NHEAD 12
#define HDIM 64
#define NQKV 2304

// Scratch (device globals; no allocation allowed)
__device__ float  g_invrms[TT * NHEAD];
__device__ __half g_xh[(size_t)TT * CC * SS];          // fp16(x * invrms * w1), [t][k][s]
__device__ __half g_wh_in[(size_t)NQKV * CC];          // fp16(Win)
__device__ __half g_wh_out[(size_t)CC * CC];           // fp16(Wout)
__device__ __half g_qkv_h[(size_t)32768 * NQKV];       // [m=t*2048+s][n] fp16
__device__ __half g_att_h[(size_t)TT * CC * SS];       // [t][c][s] fp16

__device__ __forceinline__ uint32_t packh(float lo, float hi) {
    __half2 h = __floats2half2_rn(lo, hi);
    return *(uint32_t*)&h;
}

__device__ __forceinline__ void mma_f16(float* d, const uint32_t* a, uint32_t b0, uint32_t b1) {
    asm volatile(
        "mma.sync.aligned.m16n8k16.row.col.f32.f16.f16.f32 "
        "{%0,%1,%2,%3}, {%4,%5,%6,%7}, {%8,%9}, {%0,%1,%2,%3};"
        : "+f"(d[0]), "+f"(d[1]), "+f"(d[2]), "+f"(d[3])
        : "r"(a[0]), "r"(a[1]), "r"(a[2]), "r"(a[3]), "r"(b0), "r"(b1));
}

__device__ __forceinline__ void cp16(uint32_t dst, const void* src) {
    asm volatile("cp.async.cg.shared.global [%0], [%1], 16;" :: "r"(dst), "l"(src));
}
#define CP_COMMIT() asm volatile("cp.async.commit_group;" ::: "memory")
#define CP_WAIT0()  asm volatile("cp.async.wait_group 0;" ::: "memory")

__device__ __forceinline__ void ldsm4(uint32_t* r, uint32_t addr) {
    asm volatile("ldmatrix.sync.aligned.m8n8.x4.shared.b16 {%0,%1,%2,%3}, [%4];"
        : "=r"(r[0]), "=r"(r[1]), "=r"(r[2]), "=r"(r[3]) : "r"(addr));
}
__device__ __forceinline__ void ldsm4t(uint32_t* r, uint32_t addr) {
    asm volatile("ldmatrix.sync.aligned.m8n8.x4.trans.shared.b16 {%0,%1,%2,%3}, [%4];"
        : "=r"(r[0]), "=r"(r[1]), "=r"(r[2]), "=r"(r[3]) : "r"(addr));
}

// ---------------- 1) group RMS ----------------
__global__ void rms_kernel(const float* __restrict__ x) {
    int b = blockIdx.x;
    const float4* p = (const float4*)(x + (size_t)b * 64 * SS);
    float s = 0.f;
    for (int i = threadIdx.x; i < (64 * SS) / 4; i += blockDim.x) {
        float4 v = p[i];
        s += v.x * v.x + v.y * v.y + v.z * v.z + v.w * v.w;
    }
    #pragma unroll
    for (int m = 16; m; m >>= 1) s += __shfl_xor_sync(0xffffffffu, s, m);
    __shared__ float red[8];
    if ((threadIdx.x & 31) == 0) red[threadIdx.x >> 5] = s;
    __syncthreads();
    if (threadIdx.x < 8) {
        s = red[threadIdx.x];
        #pragma unroll
        for (int m = 4; m; m >>= 1) s += __shfl_xor_sync(0xffu, s, m);
        if (threadIdx.x == 0)
            g_invrms[b] = rsqrtf(s * (1.0f / (64.0f * SS)) + 1e-6f);
    }
}

// ---------------- 1b) prep: xh = fp16(x * invrms * w1) ----------------
__global__ __launch_bounds__(256)
void convx_kernel(const float* __restrict__ x, const float* __restrict__ w1) {
    int row = blockIdx.x;
    int t = row / CC, k = row - t * CC;
    float sc = g_invrms[t * NHEAD + (k >> 6)] * w1[k];
    const float4* src = (const float4*)(x + (size_t)row * SS);
    __half* dst = g_xh + (size_t)row * SS;
    int i = threadIdx.x;
    float4 a = src[2 * i], b = src[2 * i + 1];
    uint32_t o[4] = {packh(a.x * sc, a.y * sc), packh(a.z * sc, a.w * sc),
                     packh(b.x * sc, b.y * sc), packh(b.z * sc, b.w * sc)};
    *(uint4*)(dst + i * 8) = *(uint4*)o;
}

// ---------------- 1c) prep: fp16 weight copies ----------------
__global__ __launch_bounds__(256)
void convw_kernel(const float* __restrict__ src, __half* __restrict__ dst, int n4) {
    int i = blockIdx.x * blockDim.x + threadIdx.x;
    if (i < n4) {
        float4 v = ((const float4*)src)[i];
        uint32_t o[2] = {packh(v.x, v.y), packh(v.z, v.w)};
        *(uint2*)(dst + (size_t)i * 4) = *(uint2*)o;
    }
}

// ---------------- 2/4) mma.sync fp16 GEMM (m16n8k16), pure cp.async ----------------
#define NKIT2 24
#define APADH 136
#define BPADH 40

template <int MODE>
__global__ __launch_bounds__(256, 2)
void mma_gemm(const float* __restrict__ x, const float* __restrict__ bias,
              float* __restrict__ Cout, int Nn) {
    __shared__ __half As[2][32][APADH];
    __shared__ __half Bs[2][128][BPADH];

    const int tid  = threadIdx.x;
    const int wid  = tid >> 5;
    const int lane = tid & 31;
    const int wm   = (wid & 1) * 64;
    const int wn   = (wid >> 1) * 32;
    const int lq   = lane >> 2;
    const int lr   = lane & 3;

    const int m0 = blockIdx.y * 128;
    const int n0 = blockIdx.x * 128;
    const int t  = m0 >> 11;
    const int s0 = m0 & 2047;

    const __half* Asrc = (MODE == 0) ? g_xh : g_att_h;
    const __half* Bsrc = (MODE == 0) ? g_wh_in : g_wh_out;

    const int kA_l = ((lane >> 4) << 3) + (lane & 7);
    const int mOff = (((lane >> 3) & 1) << 3);
    const int nB_l = (((lane >> 3) & 1) << 3) + (lane & 7);
    const int kB_l = ((lane >> 4) << 3);
    uint32_t aA[2][4], aB[2][2];
    #pragma unroll
    for (int p = 0; p < 2; p++) {
        #pragma unroll
        for (int im = 0; im < 4; im++)
            aA[p][im] = (uint32_t)__cvta_generic_to_shared(&As[p][kA_l][wm + im * 16 + mOff]);
        #pragma unroll
        for (int bg = 0; bg < 2; bg++)
            aB[p][bg] = (uint32_t)__cvta_generic_to_shared(&Bs[p][wn + bg * 16 + nB_l][kB_l]);
    }

    float acc[4][4][4];
    #pragma unroll
    for (int i = 0; i < 4; i++)
        #pragma unroll
        for (int j = 0; j < 4; j++)
            #pragma unroll
            for (int c = 0; c < 4; c++) acc[i][j][c] = 0.f;

    auto issueA = [&](int k0, int p) {
        #pragma unroll
        for (int r = 0; r < 2; r++) {
            int o = tid * 2 + r;
            int row = o >> 4;
            int ch  = (o & 15) * 8;
            cp16((uint32_t)__cvta_generic_to_shared(&As[p][row][ch]),
                 Asrc + ((size_t)(t * CC + k0 + row)) * SS + s0 + ch);
        }
    };
    auto issueB = [&](int k0, int p) {
        #pragma unroll
        for (int r = 0; r < 2; r++) {
            int o = tid * 2 + r;
            int row = o >> 2;
            int ch  = (o & 3) * 8;
            cp16((uint32_t)__cvta_generic_to_shared(&Bs[p][row][ch]),
                 Bsrc + (size_t)(n0 + row) * CC + k0 + ch);
        }
    };

    issueA(0, 0);
    issueB(0, 0);
    CP_COMMIT();

    for (int i = 0; i < NKIT2; i++) {
        const int p = i & 1;
        CP_WAIT0();
        __syncthreads();

        // hoist ALL fragment loads for this K-chunk (latency hidden by cp issue + mma stream)
        uint32_t af[2][4][4], bf[2][2][4];
        #pragma unroll
        for (int ks = 0; ks < 2; ks++) {
            #pragma unroll
            for (int im = 0; im < 4; im++) ldsm4t(af[ks][im], aA[p][im] + ks * (16 * APADH * 2));
            #pragma unroll
            for (int bg = 0; bg < 2; bg++) ldsm4(bf[ks][bg], aB[p][bg] + ks * 32);
        }

        if (i + 1 < NKIT2) {
            issueA((i + 1) * 32, p ^ 1);
            issueB((i + 1) * 32, p ^ 1);
            CP_COMMIT();
        }

        #pragma unroll
        for (int ks = 0; ks < 2; ks++)
            #pragma unroll
            for (int im = 0; im < 4; im++)
                #pragma unroll
                for (int in = 0; in < 4; in++)
                    mma_f16(acc[im][in], af[ks][im],
                            bf[ks][in >> 1][in & 1], bf[ks][in >> 1][(in & 1) + 2]);
    }

    // epilogue
    #pragma unroll
    for (int im = 0; im < 4; im++) {
        const int r_lo = wm + im * 16 + lq;
        const int r_hi = r_lo + 8;
        #pragma unroll
        for (int in = 0; in < 4; in++) {
            const int col = n0 + wn + in * 8 + lr * 2;
            const float b0 = bias[col], b1 = bias[col + 1];
            if (MODE == 0) {
                __half2 vlo = __floats2half2_rn(acc[im][in][0] + b0, acc[im][in][1] + b1);
                __half2 vhi = __floats2half2_rn(acc[im][in][2] + b0, acc[im][in][3] + b1);
                *(__half2*)(g_qkv_h + (size_t)(m0 + r_lo) * Nn + col) = vlo;
                *(__half2*)(g_qkv_h + (size_t)(m0 + r_hi) * Nn + col) = vhi;
            } else {
                size_t o0 = ((size_t)(t * CC + col)) * SS + s0;
                size_t o1 = ((size_t)(t * CC + col + 1)) * SS + s0;
                Cout[o0 + r_lo] = acc[im][in][0] + b0 + x[o0 + r_lo];
                Cout[o1 + r_lo] = acc[im][in][1] + b1 + x[o1 + r_lo];
                Cout[o0 + r_hi] = acc[im][in][2] + b0 + x[o0 + r_hi];
                Cout[o1 + r_hi] = acc[im][in][3] + b1 + x[o1 + r_hi];
            }
        }
    }
}

// ---------------- 3) attention: one WARP per (head, s); 8 s per block ----------------
// smem per warp: 16 rows x 200 halves (row = [q 0:64 | k 64:128 | v 128:192], pad 200)
#define QSTRIDE 200
#define ATTN_SMEM (8 * 16 * QSTRIDE * 2)

__global__ __launch_bounds__(256)
void attn_kernel(const float* __restrict__ qs, const float* __restrict__ qb,
                 const float* __restrict__ ks, const float* __restrict__ kb,
                 const float* __restrict__ relb) {
    extern __shared__ __half sh[];
    const int head  = blockIdx.x;
    const int sbase = blockIdx.y * 8;
    const int tid   = threadIdx.x;
    const int w     = tid >> 5;
    const int lane  = tid & 31;
    const int s     = sbase + w;

    __half* Q = sh + w * 16 * QSTRIDE;

    // load 16 x 192 halves (rows are 384B contiguous in g_qkv_h)
    {
        const __half* src = g_qkv_h + (size_t)s * NQKV + head * 192;
        #pragma unroll
        for (int m = lane; m < 384; m += 32) {
            int tt = m / 24, off = (m % 24) * 8;
            *(uint4*)(Q + tt * QSTRIDE + off) =
                *(const uint4*)(src + (size_t)tt * SS * NQKV + off);
        }
    }
    __syncwarp();

    // LN: lane handles one (row, q|k) pair fully; no shuffles
    {
        int r = lane & 15, which = lane >> 4;
        __half* p = Q + r * QSTRIDE + which * 64;
        float v[64];
        float sum = 0.f, ssq = 0.f;
        #pragma unroll
        for (int q8 = 0; q8 < 8; q8++) {
            uint4 u = *(uint4*)(p + q8 * 8);
            __half2* hp = (__half2*)&u;
            #pragma unroll
            for (int j = 0; j < 4; j++) {
                float2 f = __half22float2(hp[j]);
                v[q8 * 8 + j * 2]     = f.x;
                v[q8 * 8 + j * 2 + 1] = f.y;
                sum += f.x + f.y;
                ssq += f.x * f.x + f.y * f.y;
            }
        }
        float mu  = sum * (1.0f / 64.0f);
        float var = ssq * (1.0f / 64.0f) - mu * mu;
        float inv = rsqrtf(var + 1e-6f);
        const float* sc = which ? ks : qs;
        const float* bi = which ? kb : qb;
        #pragma unroll
        for (int q8 = 0; q8 < 8; q8++) {
            uint32_t o[4];
            #pragma unroll
            for (int j = 0; j < 4; j++) {
                int c = q8 * 8 + j * 2;
                o[j] = packh((v[c] - mu) * inv * sc[c] + bi[c],
                             (v[c + 1] - mu) * inv * sc[c + 1] + bi[c + 1]);
            }
            *(uint4*)(p + q8 * 8) = *(uint4*)o;
        }
    }
    __syncwarp();

    // scores + softmax: lane pair (2l, 2l+1) owns query row i = lane>>1
    const int i  = lane >> 1;
    const int j0 = (lane & 1) * 8;
    float wgt[8];
    {
        float qv[64];
        const __half* qp = Q + i * QSTRIDE;
        #pragma unroll
        for (int q8 = 0; q8 < 8; q8++) {
            uint4 u = *(const uint4*)(qp + q8 * 8);
            __half2* hp = (__half2*)&u;
            #pragma unroll
            for (int j = 0; j < 4; j++) {
                float2 f = __half22float2(hp[j]);
                qv[q8 * 8 + j * 2] = f.x; qv[q8 * 8 + j * 2 + 1] = f.y;
            }
        }
        float scv[8];
        #pragma unroll
        for (int jj = 0; jj < 8; jj++) {
            int j = j0 + jj;
            const __half* kp = Q + j * QSTRIDE + 64;
            float dot = 0.f;
            #pragma unroll
            for (int q8 = 0; q8 < 8; q8++) {
                uint4 u = *(const uint4*)(kp + q8 * 8);
                __half2* hp = (__half2*)&u;
                #pragma unroll
                for (int c = 0; c < 4; c++) {
                    float2 f = __half22float2(hp[c]);
                    dot += qv[q8 * 8 + c * 2] * f.x + qv[q8 * 8 + c * 2 + 1] * f.y;
                }
            }
            int rp = j - i;
            int bucket = (rp > 0) ? 16 : 0;
            int n = abs(rp);
            if (n < 8) bucket += n;
            else {
                int large = 8 + (int)(__logf((float)n * 0.125f) * (8.0f / 2.7725887222397811f));
                bucket += (large < 15) ? large : 15;
            }
            scv[jj] = dot * 0.125f + relb[bucket * NHEAD + head];
        }
        float mx = scv[0];
        #pragma unroll
        for (int jj = 1; jj < 8; jj++) mx = fmaxf(mx, scv[jj]);
        mx = fmaxf(mx, __shfl_xor_sync(0xffffffffu, mx, 1));
        float sm = 0.f;
        #pragma unroll
        for (int jj = 0; jj < 8; jj++) { wgt[jj] = __expf(scv[jj] - mx); sm += wgt[jj]; }
        sm += __shfl_xor_sync(0xffffffffu, sm, 1);
        float r = 1.0f / sm;
        #pragma unroll
        for (int jj = 0; jj < 8; jj++) wgt[jj] *= r;
    }

    // AV: partial over this lane's 8 t's, combine with partner, write into q slot
    {
        float outp[64];
        #pragma unroll
        for (int c = 0; c < 64; c++) outp[c] = 0.f;
        #pragma unroll
        for (int u = 0; u < 8; u++) {
            const __half* vp = Q + (j0 + u) * QSTRIDE + 128;
            float wv = wgt[u];
            #pragma unroll
            for (int q8 = 0; q8 < 8; q8++) {
                uint4 uu = *(const uint4*)(vp + q8 * 8);
                __half2* hp = (__half2*)&uu;
                #pragma unroll
                for (int c = 0; c < 4; c++) {
                    float2 f = __half22float2(hp[c]);
                    outp[q8 * 8 + c * 2]     += wv * f.x;
                    outp[q8 * 8 + c * 2 + 1] += wv * f.y;
                }
            }
        }
        #pragma unroll
        for (int c = 0; c < 64; c++)
            outp[c] += __shfl_xor_sync(0xffffffffu, outp[c], 1);
        // partner pair has finished all q reads (shuffles synced); overwrite q slot
        if (!(lane & 1)) {
            #pragma unroll
            for (int q8 = 0; q8 < 8; q8++) {
                uint32_t o[4];
                #pragma unroll
                for (int j = 0; j < 4; j++)
                    o[j] = packh(outp[q8 * 8 + j * 2], outp[q8 * 8 + j * 2 + 1]);
                *(uint4*)(Q + i * QSTRIDE + q8 * 8) = *(uint4*)o;
            }
        }
    }
    __syncthreads();

    // transposed store: 8 s-consecutive halves per (t,c) from the 8 warp slices
    for (int idx = tid; idx < 16 * 64; idx += 256) {
        int t_ = idx >> 6;
        int c  = idx & 63;
        __half h[8];
        #pragma unroll
        for (int w2 = 0; w2 < 8; w2++)
            h[w2] = sh[w2 * 16 * QSTRIDE + t_ * QSTRIDE + c];
        *(uint4*)(g_att_h + ((size_t)(t_ * CC + head * 64 + c)) * SS + sbase) = *(uint4*)h;
    }
}

extern "C" void kernel_launch(void* const* d_in, const int* in_sizes, int n_in,
                              void* d_out, int out_size) {
    const float* x    = (const float*)d_in[0];
    const float* w1   = (const float*)d_in[1];
    const float* Win  = (const float*)d_in[2];
    const float* binq = (const float*)d_in[3];
    const float* qsc  = (const float*)d_in[4];
    const float* qbi  = (const float*)d_in[5];
    const float* ksc  = (const float*)d_in[6];
    const float* kbi  = (const float*)d_in[7];
    const float* relb = (const float*)d_in[8];
    const float* Wout = (const float*)d_in[9];
    const float* bout = (const float*)d_in[10];
    float* out = (float*)d_out;

    __half *wh_in_p, *wh_out_p;
    cudaGetSymbolAddress((void**)&wh_in_p, g_wh_in);
    cudaGetSymbolAddress((void**)&wh_out_p, g_wh_out);
    cudaFuncSetAttribute(attn_kernel, cudaFuncAttributeMaxDynamicSharedMemorySize, ATTN_SMEM);

    rms_kernel<<<TT * NHEAD, 256>>>(x);
    convx_kernel<<<TT * CC, 256>>>(x, w1);
    convw_kernel<<<(NQKV * CC / 4 + 255) / 256, 256>>>(Win, wh_in_p, NQKV * CC / 4);
    convw_kernel<<<(CC * CC / 4 + 255) / 256, 256>>>(Wout, wh_out_p, CC * CC / 4);
    mma_gemm<0><<<dim3(NQKV / 128, 256), 256>>>(x, binq, nullptr, NQKV);
    attn_kernel<<<dim3(NHEAD, SS / 8), 256, ATTN_SMEM>>>(qsc, qbi, ksc, kbi, relb);
    mma_gemm<1><<<dim3(CC / 128, 256), 256>>>(x, bout, out, CC);
}

// round 12
// speedup vs baseline: 4.2130x; 1.0097x over previous
#include <cuda_runtime.h>
#include <cuda_fp16.h>
#include <cstdint>

#define TT 16
#define CC 768
#define SS 2048
#define NHEAD 12
#define HDIM 64
#define NQKV 2304

// Scratch (device globals; no allocation allowed)
__device__ __half g_xh[(size_t)TT * CC * SS];          // fp16(x * invrms * w1), [t][k][s]
__device__ __half g_wh_in[(size_t)NQKV * CC];          // fp16(Win)
__device__ __half g_wh_out[(size_t)CC * CC];           // fp16(Wout)
__device__ __half g_qkv_h[(size_t)32768 * NQKV];       // [m=t*2048+s][n] fp16
__device__ __half g_att_h[(size_t)TT * CC * SS];       // [t][c][s] fp16

__device__ __forceinline__ uint32_t packh(float lo, float hi) {
    __half2 h = __floats2half2_rn(lo, hi);
    return *(uint32_t*)&h;
}

__device__ __forceinline__ void mma_f16(float* d, const uint32_t* a, uint32_t b0, uint32_t b1) {
    asm volatile(
        "mma.sync.aligned.m16n8k16.row.col.f32.f16.f16.f32 "
        "{%0,%1,%2,%3}, {%4,%5,%6,%7}, {%8,%9}, {%0,%1,%2,%3};"
        : "+f"(d[0]), "+f"(d[1]), "+f"(d[2]), "+f"(d[3])
        : "r"(a[0]), "r"(a[1]), "r"(a[2]), "r"(a[3]), "r"(b0), "r"(b1));
}

__device__ __forceinline__ void cp16(uint32_t dst, const void* src) {
    asm volatile("cp.async.cg.shared.global [%0], [%1], 16;" :: "r"(dst), "l"(src));
}
#define CP_COMMIT() asm volatile("cp.async.commit_group;" ::: "memory")
#define CP_WAIT0()  asm volatile("cp.async.wait_group 0;" ::: "memory")

__device__ __forceinline__ void ldsm4(uint32_t* r, uint32_t addr) {
    asm volatile("ldmatrix.sync.aligned.m8n8.x4.shared.b16 {%0,%1,%2,%3}, [%4];"
        : "=r"(r[0]), "=r"(r[1]), "=r"(r[2]), "=r"(r[3]) : "r"(addr));
}
__device__ __forceinline__ void ldsm4t(uint32_t* r, uint32_t addr) {
    asm volatile("ldmatrix.sync.aligned.m8n8.x4.trans.shared.b16 {%0,%1,%2,%3}, [%4];"
        : "=r"(r[0]), "=r"(r[1]), "=r"(r[2]), "=r"(r[3]) : "r"(addr));
}

// ---------------- 1) group RMS + fp16 conversion (fused) ----------------
__global__ __launch_bounds__(256)
void rms_conv_kernel(const float* __restrict__ x, const float* __restrict__ w1) {
    int b = blockIdx.x;                       // t*NHEAD + g
    int t = b / NHEAD, g = b - t * NHEAD;
    const float4* p = (const float4*)(x + (size_t)b * 64 * SS);
    float s = 0.f;
    for (int i = threadIdx.x; i < (64 * SS) / 4; i += 256) {
        float4 v = p[i];
        s += v.x * v.x + v.y * v.y + v.z * v.z + v.w * v.w;
    }
    #pragma unroll
    for (int m = 16; m; m >>= 1) s += __shfl_xor_sync(0xffffffffu, s, m);
    __shared__ float red[8];
    __shared__ float s_inv;
    if ((threadIdx.x & 31) == 0) red[threadIdx.x >> 5] = s;
    __syncthreads();
    if (threadIdx.x == 0) {
        float tot = 0.f;
        #pragma unroll
        for (int j = 0; j < 8; j++) tot += red[j];
        s_inv = rsqrtf(tot * (1.0f / (64.0f * SS)) + 1e-6f);
    }
    __syncthreads();
    const float inv = s_inv;

    // pass 2: scale + fp16 write (reads hit L2)
    for (int i = threadIdx.x; i < (64 * SS) / 8; i += 256) {
        int row = i >> 8;                       // SS/8 = 256 chunks per row
        int off = (i & 255) * 8;
        float sc = inv * w1[g * 64 + row];
        const float4* src = (const float4*)(x + ((size_t)b * 64 + row) * SS + off);
        float4 a = src[0], c = src[1];
        uint32_t o[4] = {packh(a.x * sc, a.y * sc), packh(a.z * sc, a.w * sc),
                         packh(c.x * sc, c.y * sc), packh(c.z * sc, c.w * sc)};
        *(uint4*)(g_xh + ((size_t)(t * CC + g * 64 + row)) * SS + off) = *(uint4*)o;
    }
}

// ---------------- 1c) prep: fp16 weight copies ----------------
__global__ __launch_bounds__(256)
void convw_kernel(const float* __restrict__ src, __half* __restrict__ dst, int n4) {
    int i = blockIdx.x * blockDim.x + threadIdx.x;
    if (i < n4) {
        float4 v = ((const float4*)src)[i];
        uint32_t o[2] = {packh(v.x, v.y), packh(v.z, v.w)};
        *(uint2*)(dst + (size_t)i * 4) = *(uint2*)o;
    }
}

// ---------------- 2/4) mma.sync fp16 GEMM (m16n8k16), pure cp.async ----------------
#define NKIT2 24
#define APADH 136
#define BPADH 40
#define SMEM_RAW ((2 * 32 * APADH + 2 * 128 * BPADH) * 2)   // 37888 bytes

template <int MODE>
__global__ __launch_bounds__(256, 2)
void mma_gemm(const float* __restrict__ x, const float* __restrict__ bias,
              float* __restrict__ Cout, int Nn) {
    __shared__ __align__(16) char smem_raw[SMEM_RAW];
    __half (*As)[32][APADH]  = (__half (*)[32][APADH])smem_raw;
    __half (*Bs)[128][BPADH] = (__half (*)[128][BPADH])(smem_raw + 2 * 32 * APADH * 2);
    float (*stg)[16][68]     = (float (*)[16][68])smem_raw;   // per-warp epilogue staging

    const int tid  = threadIdx.x;
    const int wid  = tid >> 5;
    const int lane = tid & 31;
    const int wm   = (wid & 1) * 64;
    const int wn   = (wid >> 1) * 32;
    const int lq   = lane >> 2;
    const int lr   = lane & 3;

    const int m0 = blockIdx.y * 128;
    const int n0 = blockIdx.x * 128;
    const int t  = m0 >> 11;
    const int s0 = m0 & 2047;

    const __half* Asrc = (MODE == 0) ? g_xh : g_att_h;
    const __half* Bsrc = (MODE == 0) ? g_wh_in : g_wh_out;

    const int kA_l = ((lane >> 4) << 3) + (lane & 7);
    const int mOff = (((lane >> 3) & 1) << 3);
    const int nB_l = (((lane >> 3) & 1) << 3) + (lane & 7);
    const int kB_l = ((lane >> 4) << 3);
    uint32_t aA[2][4], aB[2][2];
    #pragma unroll
    for (int p = 0; p < 2; p++) {
        #pragma unroll
        for (int im = 0; im < 4; im++)
            aA[p][im] = (uint32_t)__cvta_generic_to_shared(&As[p][kA_l][wm + im * 16 + mOff]);
        #pragma unroll
        for (int bg = 0; bg < 2; bg++)
            aB[p][bg] = (uint32_t)__cvta_generic_to_shared(&Bs[p][wn + bg * 16 + nB_l][kB_l]);
    }

    float acc[4][4][4];
    #pragma unroll
    for (int i = 0; i < 4; i++)
        #pragma unroll
        for (int j = 0; j < 4; j++)
            #pragma unroll
            for (int c = 0; c < 4; c++) acc[i][j][c] = 0.f;

    auto issueA = [&](int k0, int p) {
        #pragma unroll
        for (int r = 0; r < 2; r++) {
            int o = tid * 2 + r;
            int row = o >> 4;
            int ch  = (o & 15) * 8;
            cp16((uint32_t)__cvta_generic_to_shared(&As[p][row][ch]),
                 Asrc + ((size_t)(t * CC + k0 + row)) * SS + s0 + ch);
        }
    };
    auto issueB = [&](int k0, int p) {
        #pragma unroll
        for (int r = 0; r < 2; r++) {
            int o = tid * 2 + r;
            int row = o >> 2;
            int ch  = (o & 3) * 8;
            cp16((uint32_t)__cvta_generic_to_shared(&Bs[p][row][ch]),
                 Bsrc + (size_t)(n0 + row) * CC + k0 + ch);
        }
    };

    issueA(0, 0);
    issueB(0, 0);
    CP_COMMIT();

    for (int i = 0; i < NKIT2; i++) {
        const int p = i & 1;
        CP_WAIT0();
        __syncthreads();

        uint32_t af[2][4][4], bf[2][2][4];
        #pragma unroll
        for (int ks = 0; ks < 2; ks++) {
            #pragma unroll
            for (int im = 0; im < 4; im++) ldsm4t(af[ks][im], aA[p][im] + ks * (16 * APADH * 2));
            #pragma unroll
            for (int bg = 0; bg < 2; bg++) ldsm4(bf[ks][bg], aB[p][bg] + ks * 32);
        }

        if (i + 1 < NKIT2) {
            issueA((i + 1) * 32, p ^ 1);
            issueB((i + 1) * 32, p ^ 1);
            CP_COMMIT();
        }

        #pragma unroll
        for (int ks = 0; ks < 2; ks++)
            #pragma unroll
            for (int im = 0; im < 4; im++)
                #pragma unroll
                for (int in = 0; in < 4; in++)
                    mma_f16(acc[im][in], af[ks][im],
                            bf[ks][in >> 1][in & 1], bf[ks][in >> 1][(in & 1) + 2]);
    }

    if (MODE == 0) {
        // direct fp16 stores (write-merge friendly enough)
        #pragma unroll
        for (int im = 0; im < 4; im++) {
            const int r_lo = wm + im * 16 + lq;
            const int r_hi = r_lo + 8;
            #pragma unroll
            for (int in = 0; in < 4; in++) {
                const int col = n0 + wn + in * 8 + lr * 2;
                const float b0 = bias[col], b1 = bias[col + 1];
                __half2 vlo = __floats2half2_rn(acc[im][in][0] + b0, acc[im][in][1] + b1);
                __half2 vhi = __floats2half2_rn(acc[im][in][2] + b0, acc[im][in][3] + b1);
                *(__half2*)(g_qkv_h + (size_t)(m0 + r_lo) * Nn + col) = vlo;
                *(__half2*)(g_qkv_h + (size_t)(m0 + r_hi) * Nn + col) = vhi;
            }
        }
    } else {
        // smem-staged epilogue: coalesced 256B runs along s for store AND residual read
        __syncthreads();   // all warps done with As/Bs before overlay reuse
        #pragma unroll
        for (int pass = 0; pass < 2; pass++) {
            #pragma unroll
            for (int im = 0; im < 4; im++) {
                #pragma unroll
                for (int inl = 0; inl < 2; inl++) {
                    const int in = pass * 2 + inl;
                    const int cp = inl * 8 + lr * 2;
                    stg[wid][cp][im * 16 + lq]         = acc[im][in][0];
                    stg[wid][cp + 1][im * 16 + lq]     = acc[im][in][1];
                    stg[wid][cp][im * 16 + lq + 8]     = acc[im][in][2];
                    stg[wid][cp + 1][im * 16 + lq + 8] = acc[im][in][3];
                }
            }
            __syncwarp();
            #pragma unroll
            for (int c = 0; c < 16; c++) {
                const int col = n0 + wn + pass * 16 + c;
                const float b = bias[col];
                size_t o = ((size_t)(t * CC + col)) * SS + s0 + wm + lane * 2;
                float2 v  = *(float2*)&stg[wid][c][lane * 2];
                float2 xr = *(const float2*)(x + o);
                *(float2*)(Cout + o) = make_float2(v.x + b + xr.x, v.y + b + xr.y);
            }
            __syncwarp();
        }
    }
}

// ---------------- 3) attention: one WARP per (head, s); 8 s per block ----------------
#define QSTRIDE 200
#define ATTN_SMEM (8 * 16 * QSTRIDE * 2)

__global__ __launch_bounds__(256)
void attn_kernel(const float* __restrict__ qs, const float* __restrict__ qb,
                 const float* __restrict__ ks, const float* __restrict__ kb,
                 const float* __restrict__ relb) {
    extern __shared__ __half sh[];
    const int head  = blockIdx.x;
    const int sbase = blockIdx.y * 8;
    const int tid   = threadIdx.x;
    const int w     = tid >> 5;
    const int lane  = tid & 31;
    const int s     = sbase + w;

    __half* Q = sh + w * 16 * QSTRIDE;

    {
        const __half* src = g_qkv_h + (size_t)s * NQKV + head * 192;
        #pragma unroll
        for (int m = lane; m < 384; m += 32) {
            int tt = m / 24, off = (m % 24) * 8;
            *(uint4*)(Q + tt * QSTRIDE + off) =
                *(const uint4*)(src + (size_t)tt * SS * NQKV + off);
        }
    }
    __syncwarp();

    {
        int r = lane & 15, which = lane >> 4;
        __half* p = Q + r * QSTRIDE + which * 64;
        float v[64];
        float sum = 0.f, ssq = 0.f;
        #pragma unroll
        for (int q8 = 0; q8 < 8; q8++) {
            uint4 u = *(uint4*)(p + q8 * 8);
            __half2* hp = (__half2*)&u;
            #pragma unroll
            for (int j = 0; j < 4; j++) {
                float2 f = __half22float2(hp[j]);
                v[q8 * 8 + j * 2]     = f.x;
                v[q8 * 8 + j * 2 + 1] = f.y;
                sum += f.x + f.y;
                ssq += f.x * f.x + f.y * f.y;
            }
        }
        float mu  = sum * (1.0f / 64.0f);
        float var = ssq * (1.0f / 64.0f) - mu * mu;
        float inv = rsqrtf(var + 1e-6f);
        const float* sc = which ? ks : qs;
        const float* bi = which ? kb : qb;
        #pragma unroll
        for (int q8 = 0; q8 < 8; q8++) {
            uint32_t o[4];
            #pragma unroll
            for (int j = 0; j < 4; j++) {
                int c = q8 * 8 + j * 2;
                o[j] = packh((v[c] - mu) * inv * sc[c] + bi[c],
                             (v[c + 1] - mu) * inv * sc[c + 1] + bi[c + 1]);
            }
            *(uint4*)(p + q8 * 8) = *(uint4*)o;
        }
    }
    __syncwarp();

    const int i  = lane >> 1;
    const int j0 = (lane & 1) * 8;
    float wgt[8];
    {
        float qv[64];
        const __half* qp = Q + i * QSTRIDE;
        #pragma unroll
        for (int q8 = 0; q8 < 8; q8++) {
            uint4 u = *(const uint4*)(qp + q8 * 8);
            __half2* hp = (__half2*)&u;
            #pragma unroll
            for (int j = 0; j < 4; j++) {
                float2 f = __half22float2(hp[j]);
                qv[q8 * 8 + j * 2] = f.x; qv[q8 * 8 + j * 2 + 1] = f.y;
            }
        }
        float scv[8];
        #pragma unroll
        for (int jj = 0; jj < 8; jj++) {
            int j = j0 + jj;
            const __half* kp = Q + j * QSTRIDE + 64;
            float dot = 0.f;
            #pragma unroll
            for (int q8 = 0; q8 < 8; q8++) {
                uint4 u = *(const uint4*)(kp + q8 * 8);
                __half2* hp = (__half2*)&u;
                #pragma unroll
                for (int c = 0; c < 4; c++) {
                    float2 f = __half22float2(hp[c]);
                    dot += qv[q8 * 8 + c * 2] * f.x + qv[q8 * 8 + c * 2 + 1] * f.y;
                }
            }
            int rp = j - i;
            int bucket = (rp > 0) ? 16 : 0;
            int n = abs(rp);
            if (n < 8) bucket += n;
            else {
                int large = 8 + (int)(__logf((float)n * 0.125f) * (8.0f / 2.7725887222397811f));
                bucket += (large < 15) ? large : 15;
            }
            scv[jj] = dot * 0.125f + relb[bucket * NHEAD + head];
        }
        float mx = scv[0];
        #pragma unroll
        for (int jj = 1; jj < 8; jj++) mx = fmaxf(mx, scv[jj]);
        mx = fmaxf(mx, __shfl_xor_sync(0xffffffffu, mx, 1));
        float sm = 0.f;
        #pragma unroll
        for (int jj = 0; jj < 8; jj++) { wgt[jj] = __expf(scv[jj] - mx); sm += wgt[jj]; }
        sm += __shfl_xor_sync(0xffffffffu, sm, 1);
        float r = 1.0f / sm;
        #pragma unroll
        for (int jj = 0; jj < 8; jj++) wgt[jj] *= r;
    }

    {
        float outp[64];
        #pragma unroll
        for (int c = 0; c < 64; c++) outp[c] = 0.f;
        #pragma unroll
        for (int u = 0; u < 8; u++) {
            const __half* vp = Q + (j0 + u) * QSTRIDE + 128;
            float wv = wgt[u];
            #pragma unroll
            for (int q8 = 0; q8 < 8; q8++) {
                uint4 uu = *(const uint4*)(vp + q8 * 8);
                __half2* hp = (__half2*)&uu;
                #pragma unroll
                for (int c = 0; c < 4; c++) {
                    float2 f = __half22float2(hp[c]);
                    outp[q8 * 8 + c * 2]     += wv * f.x;
                    outp[q8 * 8 + c * 2 + 1] += wv * f.y;
                }
            }
        }
        #pragma unroll
        for (int c = 0; c < 64; c++)
            outp[c] += __shfl_xor_sync(0xffffffffu, outp[c], 1);
        if (!(lane & 1)) {
            #pragma unroll
            for (int q8 = 0; q8 < 8; q8++) {
                uint32_t o[4];
                #pragma unroll
                for (int j = 0; j < 4; j++)
                    o[j] = packh(outp[q8 * 8 + j * 2], outp[q8 * 8 + j * 2 + 1]);
                *(uint4*)(Q + i * QSTRIDE + q8 * 8) = *(uint4*)o;
            }
        }
    }
    __syncthreads();

    for (int idx = tid; idx < 16 * 64; idx += 256) {
        int t_ = idx >> 6;
        int c  = idx & 63;
        __half h[8];
        #pragma unroll
        for (int w2 = 0; w2 < 8; w2++)
            h[w2] = sh[w2 * 16 * QSTRIDE + t_ * QSTRIDE + c];
        *(uint4*)(g_att_h + ((size_t)(t_ * CC + head * 64 + c)) * SS + sbase) = *(uint4*)h;
    }
}

extern "C" void kernel_launch(void* const* d_in, const int* in_sizes, int n_in,
                              void* d_out, int out_size) {
    const float* x    = (const float*)d_in[0];
    const float* w1   = (const float*)d_in[1];
    const float* Win  = (const float*)d_in[2];
    const float* binq = (const float*)d_in[3];
    const float* qsc  = (const float*)d_in[4];
    const float* qbi  = (const float*)d_in[5];
    const float* ksc  = (const float*)d_in[6];
    const float* kbi  = (const float*)d_in[7];
    const float* relb = (const float*)d_in[8];
    const float* Wout = (const float*)d_in[9];
    const float* bout = (const float*)d_in[10];
    float* out = (float*)d_out;

    __half *wh_in_p, *wh_out_p;
    cudaGetSymbolAddress((void**)&wh_in_p, g_wh_in);
    cudaGetSymbolAddress((void**)&wh_out_p, g_wh_out);
    cudaFuncSetAttribute(attn_kernel, cudaFuncAttributeMaxDynamicSharedMemorySize, ATTN_SMEM);

    rms_conv_kernel<<<TT * NHEAD, 256>>>(x, w1);
    convw_kernel<<<(NQKV * CC / 4 + 255) / 256, 256>>>(Win, wh_in_p, NQKV * CC / 4);
    convw_kernel<<<(CC * CC / 4 + 255) / 256, 256>>>(Wout, wh_out_p, CC * CC / 4);
    mma_gemm<0><<<dim3(NQKV / 128, 256), 256>>>(x, binq, nullptr, NQKV);
    attn_kernel<<<dim3(NHEAD, SS / 8), 256, ATTN_SMEM>>>(qsc, qbi, ksc, kbi, relb);
    mma_gemm<1><<<dim3(CC / 128, 256), 256>>>(x, bout, out, CC);
}

// round 13
// speedup vs baseline: 4.3682x; 1.0368x over previous
#include <cuda_runtime.h>
#include <cuda_fp16.h>
#include <cstdint>

#define TT 16
#define CC 768
#define SS 2048
#define NHEAD 12
#define HDIM 64
#define NQKV 2304

// Scratch (device globals; no allocation allowed)
__device__ __half g_xh[(size_t)TT * CC * SS];          // fp16(x * invrms * w1), [t][k][s]
__device__ __half g_wh_in[(size_t)NQKV * CC];          // fp16(Win)
__device__ __half g_wh_out[(size_t)CC * CC];           // fp16(Wout)
__device__ __half g_qkv_h[(size_t)32768 * NQKV];       // [m=t*2048+s][n] fp16
__device__ __half g_att_h[(size_t)TT * CC * SS];       // [t][c][s] fp16

__device__ __forceinline__ uint32_t packh(float lo, float hi) {
    __half2 h = __floats2half2_rn(lo, hi);
    return *(uint32_t*)&h;
}

__device__ __forceinline__ void mma_f16(float* d, const uint32_t* a, uint32_t b0, uint32_t b1) {
    asm volatile(
        "mma.sync.aligned.m16n8k16.row.col.f32.f16.f16.f32 "
        "{%0,%1,%2,%3}, {%4,%5,%6,%7}, {%8,%9}, {%0,%1,%2,%3};"
        : "+f"(d[0]), "+f"(d[1]), "+f"(d[2]), "+f"(d[3])
        : "r"(a[0]), "r"(a[1]), "r"(a[2]), "r"(a[3]), "r"(b0), "r"(b1));
}

__device__ __forceinline__ void cp16(uint32_t dst, const void* src) {
    asm volatile("cp.async.cg.shared.global [%0], [%1], 16;" :: "r"(dst), "l"(src));
}
#define CP_COMMIT() asm volatile("cp.async.commit_group;" ::: "memory")
#define CP_WAIT2()  asm volatile("cp.async.wait_group 2;" ::: "memory")

__device__ __forceinline__ void ldsm4(uint32_t* r, uint32_t addr) {
    asm volatile("ldmatrix.sync.aligned.m8n8.x4.shared.b16 {%0,%1,%2,%3}, [%4];"
        : "=r"(r[0]), "=r"(r[1]), "=r"(r[2]), "=r"(r[3]) : "r"(addr));
}
__device__ __forceinline__ void ldsm4t(uint32_t* r, uint32_t addr) {
    asm volatile("ldmatrix.sync.aligned.m8n8.x4.trans.shared.b16 {%0,%1,%2,%3}, [%4];"
        : "=r"(r[0]), "=r"(r[1]), "=r"(r[2]), "=r"(r[3]) : "r"(addr));
}

// ---------------- 1) group RMS + fp16 conversion (fused) ----------------
__global__ __launch_bounds__(256)
void rms_conv_kernel(const float* __restrict__ x, const float* __restrict__ w1) {
    int b = blockIdx.x;
    int t = b / NHEAD, g = b - t * NHEAD;
    const float4* p = (const float4*)(x + (size_t)b * 64 * SS);
    float s = 0.f;
    for (int i = threadIdx.x; i < (64 * SS) / 4; i += 256) {
        float4 v = p[i];
        s += v.x * v.x + v.y * v.y + v.z * v.z + v.w * v.w;
    }
    #pragma unroll
    for (int m = 16; m; m >>= 1) s += __shfl_xor_sync(0xffffffffu, s, m);
    __shared__ float red[8];
    __shared__ float s_inv;
    if ((threadIdx.x & 31) == 0) red[threadIdx.x >> 5] = s;
    __syncthreads();
    if (threadIdx.x == 0) {
        float tot = 0.f;
        #pragma unroll
        for (int j = 0; j < 8; j++) tot += red[j];
        s_inv = rsqrtf(tot * (1.0f / (64.0f * SS)) + 1e-6f);
    }
    __syncthreads();
    const float inv = s_inv;

    for (int i = threadIdx.x; i < (64 * SS) / 8; i += 256) {
        int row = i >> 8;
        int off = (i & 255) * 8;
        float sc = inv * w1[g * 64 + row];
        const float4* src = (const float4*)(x + ((size_t)b * 64 + row) * SS + off);
        float4 a = src[0], c = src[1];
        uint32_t o[4] = {packh(a.x * sc, a.y * sc), packh(a.z * sc, a.w * sc),
                         packh(c.x * sc, c.y * sc), packh(c.z * sc, c.w * sc)};
        *(uint4*)(g_xh + ((size_t)(t * CC + g * 64 + row)) * SS + off) = *(uint4*)o;
    }
}

// ---------------- 1c) prep: fp16 weight copies ----------------
__global__ __launch_bounds__(256)
void convw_kernel(const float* __restrict__ src, __half* __restrict__ dst, int n4) {
    int i = blockIdx.x * blockDim.x + threadIdx.x;
    if (i < n4) {
        float4 v = ((const float4*)src)[i];
        uint32_t o[2] = {packh(v.x, v.y), packh(v.z, v.w)};
        *(uint2*)(dst + (size_t)i * 4) = *(uint2*)o;
    }
}

// ---------------- 2/4) mma.sync fp16 GEMM, 4-stage cp.async ----------------
#define NKIT2 24
#define APADH 136
#define BPADH 40
#define ASTG_H (32 * APADH)                 // halves per A stage
#define BSTG_H (128 * BPADH)
#define ASTG_BYTES (ASTG_H * 2)             // 8704
#define BSTG_BYTES (BSTG_H * 2)             // 10240
#define GEMM_SMEM (4 * (ASTG_BYTES + BSTG_BYTES))   // 75776

template <int MODE>
__global__ __launch_bounds__(256, 2)
void mma_gemm(const float* __restrict__ x, const float* __restrict__ bias,
              float* __restrict__ Cout, int Nn) {
    extern __shared__ __align__(16) char smem_raw[];
    __half (*As)[32][APADH]  = (__half (*)[32][APADH])smem_raw;
    __half (*Bs)[128][BPADH] = (__half (*)[128][BPADH])(smem_raw + 4 * ASTG_BYTES);
    float (*stg)[16][68]     = (float (*)[16][68])smem_raw;   // MODE 1 epilogue overlay

    const int tid  = threadIdx.x;
    const int wid  = tid >> 5;
    const int lane = tid & 31;
    const int wm   = (wid & 1) * 64;
    const int wn   = (wid >> 1) * 32;
    const int lq   = lane >> 2;
    const int lr   = lane & 3;

    const int m0 = blockIdx.y * 128;
    const int n0 = blockIdx.x * 128;
    const int t  = m0 >> 11;
    const int s0 = m0 & 2047;

    const __half* Asrc = (MODE == 0) ? g_xh : g_att_h;
    const __half* Bsrc = (MODE == 0) ? g_wh_in : g_wh_out;

    // ldmatrix lane base addresses (stage 0)
    const int kA_l = ((lane >> 4) << 3) + (lane & 7);
    const int mOff = (((lane >> 3) & 1) << 3);
    const int nB_l = (((lane >> 3) & 1) << 3) + (lane & 7);
    const int kB_l = ((lane >> 4) << 3);
    uint32_t aA0[4], aB0[2];
    #pragma unroll
    for (int im = 0; im < 4; im++)
        aA0[im] = (uint32_t)__cvta_generic_to_shared(&As[0][kA_l][wm + im * 16 + mOff]);
    #pragma unroll
    for (int bg = 0; bg < 2; bg++)
        aB0[bg] = (uint32_t)__cvta_generic_to_shared(&Bs[0][wn + bg * 16 + nB_l][kB_l]);

    float acc[4][4][4];
    #pragma unroll
    for (int i = 0; i < 4; i++)
        #pragma unroll
        for (int j = 0; j < 4; j++)
            #pragma unroll
            for (int c = 0; c < 4; c++) acc[i][j][c] = 0.f;

    auto issueA = [&](int k0, int p) {
        #pragma unroll
        for (int r = 0; r < 2; r++) {
            int o = tid * 2 + r;
            int row = o >> 4;
            int ch  = (o & 15) * 8;
            cp16((uint32_t)__cvta_generic_to_shared(&As[p][row][ch]),
                 Asrc + ((size_t)(t * CC + k0 + row)) * SS + s0 + ch);
        }
    };
    auto issueB = [&](int k0, int p) {
        #pragma unroll
        for (int r = 0; r < 2; r++) {
            int o = tid * 2 + r;
            int row = o >> 2;
            int ch  = (o & 3) * 8;
            cp16((uint32_t)__cvta_generic_to_shared(&Bs[p][row][ch]),
                 Bsrc + (size_t)(n0 + row) * CC + k0 + ch);
        }
    };

    // prologue: stages 0,1,2 as groups g0,g1,g2
    #pragma unroll
    for (int p = 0; p < 3; p++) {
        issueA(p * 32, p);
        issueB(p * 32, p);
        CP_COMMIT();
    }

    for (int i = 0; i < NKIT2; i++) {
        const int p = i & 3;
        // group g(i) holds stage p's data; ≤2 outstanding completes it
        CP_WAIT2();
        __syncthreads();

        const uint32_t aoff = (uint32_t)(p * ASTG_BYTES);
        const uint32_t boff = (uint32_t)(p * BSTG_BYTES);
        uint32_t af[2][4][4], bf[2][2][4];
        #pragma unroll
        for (int ks = 0; ks < 2; ks++) {
            #pragma unroll
            for (int im = 0; im < 4; im++)
                ldsm4t(af[ks][im], aA0[im] + aoff + ks * (16 * APADH * 2));
            #pragma unroll
            for (int bg = 0; bg < 2; bg++)
                ldsm4(bf[ks][bg], aB0[bg] + boff + ks * 32);
        }

        if (i + 3 < NKIT2) {
            const int pn = (i + 3) & 3;
            issueA((i + 3) * 32, pn);
            issueB((i + 3) * 32, pn);
        }
        CP_COMMIT();   // always commit (possibly empty) to keep group accounting fixed

        #pragma unroll
        for (int ks = 0; ks < 2; ks++)
            #pragma unroll
            for (int im = 0; im < 4; im++)
                #pragma unroll
                for (int in = 0; in < 4; in++)
                    mma_f16(acc[im][in], af[ks][im],
                            bf[ks][in >> 1][in & 1], bf[ks][in >> 1][(in & 1) + 2]);
    }

    if (MODE == 0) {
        #pragma unroll
        for (int im = 0; im < 4; im++) {
            const int r_lo = wm + im * 16 + lq;
            const int r_hi = r_lo + 8;
            #pragma unroll
            for (int in = 0; in < 4; in++) {
                const int col = n0 + wn + in * 8 + lr * 2;
                const float b0 = bias[col], b1 = bias[col + 1];
                __half2 vlo = __floats2half2_rn(acc[im][in][0] + b0, acc[im][in][1] + b1);
                __half2 vhi = __floats2half2_rn(acc[im][in][2] + b0, acc[im][in][3] + b1);
                *(__half2*)(g_qkv_h + (size_t)(m0 + r_lo) * Nn + col) = vlo;
                *(__half2*)(g_qkv_h + (size_t)(m0 + r_hi) * Nn + col) = vhi;
            }
        }
    } else {
        __syncthreads();
        #pragma unroll
        for (int pass = 0; pass < 2; pass++) {
            #pragma unroll
            for (int im = 0; im < 4; im++) {
                #pragma unroll
                for (int inl = 0; inl < 2; inl++) {
                    const int in = pass * 2 + inl;
                    const int cp = inl * 8 + lr * 2;
                    stg[wid][cp][im * 16 + lq]         = acc[im][in][0];
                    stg[wid][cp + 1][im * 16 + lq]     = acc[im][in][1];
                    stg[wid][cp][im * 16 + lq + 8]     = acc[im][in][2];
                    stg[wid][cp + 1][im * 16 + lq + 8] = acc[im][in][3];
                }
            }
            __syncwarp();
            #pragma unroll
            for (int c = 0; c < 16; c++) {
                const int col = n0 + wn + pass * 16 + c;
                const float b = bias[col];
                size_t o = ((size_t)(t * CC + col)) * SS + s0 + wm + lane * 2;
                float2 v  = *(float2*)&stg[wid][c][lane * 2];
                float2 xr = *(const float2*)(x + o);
                *(float2*)(Cout + o) = make_float2(v.x + b + xr.x, v.y + b + xr.y);
            }
            __syncwarp();
        }
    }
}

// ---------------- 3) attention: one WARP per (head, s); 8 s per block ----------------
#define QSTRIDE 200
#define ATTN_SMEM (8 * 16 * QSTRIDE * 2)

__global__ __launch_bounds__(256)
void attn_kernel(const float* __restrict__ qs, const float* __restrict__ qb,
                 const float* __restrict__ ks, const float* __restrict__ kb,
                 const float* __restrict__ relb) {
    extern __shared__ __half sh[];
    const int head  = blockIdx.x;
    const int sbase = blockIdx.y * 8;
    const int tid   = threadIdx.x;
    const int w     = tid >> 5;
    const int lane  = tid & 31;
    const int s     = sbase + w;

    __half* Q = sh + w * 16 * QSTRIDE;

    {
        const __half* src = g_qkv_h + (size_t)s * NQKV + head * 192;
        #pragma unroll
        for (int m = lane; m < 384; m += 32) {
            int tt = m / 24, off = (m % 24) * 8;
            *(uint4*)(Q + tt * QSTRIDE + off) =
                *(const uint4*)(src + (size_t)tt * SS * NQKV + off);
        }
    }
    __syncwarp();

    {
        int r = lane & 15, which = lane >> 4;
        __half* p = Q + r * QSTRIDE + which * 64;
        float v[64];
        float sum = 0.f, ssq = 0.f;
        #pragma unroll
        for (int q8 = 0; q8 < 8; q8++) {
            uint4 u = *(uint4*)(p + q8 * 8);
            __half2* hp = (__half2*)&u;
            #pragma unroll
            for (int j = 0; j < 4; j++) {
                float2 f = __half22float2(hp[j]);
                v[q8 * 8 + j * 2]     = f.x;
                v[q8 * 8 + j * 2 + 1] = f.y;
                sum += f.x + f.y;
                ssq += f.x * f.x + f.y * f.y;
            }
        }
        float mu  = sum * (1.0f / 64.0f);
        float var = ssq * (1.0f / 64.0f) - mu * mu;
        float inv = rsqrtf(var + 1e-6f);
        const float* sc = which ? ks : qs;
        const float* bi = which ? kb : qb;
        #pragma unroll
        for (int q8 = 0; q8 < 8; q8++) {
            uint32_t o[4];
            #pragma unroll
            for (int j = 0; j < 4; j++) {
                int c = q8 * 8 + j * 2;
                o[j] = packh((v[c] - mu) * inv * sc[c] + bi[c],
                             (v[c + 1] - mu) * inv * sc[c + 1] + bi[c + 1]);
            }
            *(uint4*)(p + q8 * 8) = *(uint4*)o;
        }
    }
    __syncwarp();

    const int i  = lane >> 1;
    const int j0 = (lane & 1) * 8;
    float wgt[8];
    {
        float qv[64];
        const __half* qp = Q + i * QSTRIDE;
        #pragma unroll
        for (int q8 = 0; q8 < 8; q8++) {
            uint4 u = *(const uint4*)(qp + q8 * 8);
            __half2* hp = (__half2*)&u;
            #pragma unroll
            for (int j = 0; j < 4; j++) {
                float2 f = __half22float2(hp[j]);
                qv[q8 * 8 + j * 2] = f.x; qv[q8 * 8 + j * 2 + 1] = f.y;
            }
        }
        float scv[8];
        #pragma unroll
        for (int jj = 0; jj < 8; jj++) {
            int j = j0 + jj;
            const __half* kp = Q + j * QSTRIDE + 64;
            float dot = 0.f;
            #pragma unroll
            for (int q8 = 0; q8 < 8; q8++) {
                uint4 u = *(const uint4*)(kp + q8 * 8);
                __half2* hp = (__half2*)&u;
                #pragma unroll
                for (int c = 0; c < 4; c++) {
                    float2 f = __half22float2(hp[c]);
                    dot += qv[q8 * 8 + c * 2] * f.x + qv[q8 * 8 + c * 2 + 1] * f.y;
                }
            }
            int rp = j - i;
            int bucket = (rp > 0) ? 16 : 0;
            int n = abs(rp);
            if (n < 8) bucket += n;
            else {
                int large = 8 + (int)(__logf((float)n * 0.125f) * (8.0f / 2.7725887222397811f));
                bucket += (large < 15) ? large : 15;
            }
            scv[jj] = dot * 0.125f + relb[bucket * NHEAD + head];
        }
        float mx = scv[0];
        #pragma unroll
        for (int jj = 1; jj < 8; jj++) mx = fmaxf(mx, scv[jj]);
        mx = fmaxf(mx, __shfl_xor_sync(0xffffffffu, mx, 1));
        float sm = 0.f;
        #pragma unroll
        for (int jj = 0; jj < 8; jj++) { wgt[jj] = __expf(scv[jj] - mx); sm += wgt[jj]; }
        sm += __shfl_xor_sync(0xffffffffu, sm, 1);
        float r = 1.0f / sm;
        #pragma unroll
        for (int jj = 0; jj < 8; jj++) wgt[jj] *= r;
    }

    {
        float outp[64];
        #pragma unroll
        for (int c = 0; c < 64; c++) outp[c] = 0.f;
        #pragma unroll
        for (int u = 0; u < 8; u++) {
            const __half* vp = Q + (j0 + u) * QSTRIDE + 128;
            float wv = wgt[u];
            #pragma unroll
            for (int q8 = 0; q8 < 8; q8++) {
                uint4 uu = *(const uint4*)(vp + q8 * 8);
                __half2* hp = (__half2*)&uu;
                #pragma unroll
                for (int c = 0; c < 4; c++) {
                    float2 f = __half22float2(hp[c]);
                    outp[q8 * 8 + c * 2]     += wv * f.x;
                    outp[q8 * 8 + c * 2 + 1] += wv * f.y;
                }
            }
        }
        #pragma unroll
        for (int c = 0; c < 64; c++)
            outp[c] += __shfl_xor_sync(0xffffffffu, outp[c], 1);
        if (!(lane & 1)) {
            #pragma unroll
            for (int q8 = 0; q8 < 8; q8++) {
                uint32_t o[4];
                #pragma unroll
                for (int j = 0; j < 4; j++)
                    o[j] = packh(outp[q8 * 8 + j * 2], outp[q8 * 8 + j * 2 + 1]);
                *(uint4*)(Q + i * QSTRIDE + q8 * 8) = *(uint4*)o;
            }
        }
    }
    __syncthreads();

    for (int idx = tid; idx < 16 * 64; idx += 256) {
        int t_ = idx >> 6;
        int c  = idx & 63;
        __half h[8];
        #pragma unroll
        for (int w2 = 0; w2 < 8; w2++)
            h[w2] = sh[w2 * 16 * QSTRIDE + t_ * QSTRIDE + c];
        *(uint4*)(g_att_h + ((size_t)(t_ * CC + head * 64 + c)) * SS + sbase) = *(uint4*)h;
    }
}

extern "C" void kernel_launch(void* const* d_in, const int* in_sizes, int n_in,
                              void* d_out, int out_size) {
    const float* x    = (const float*)d_in[0];
    const float* w1   = (const float*)d_in[1];
    const float* Win  = (const float*)d_in[2];
    const float* binq = (const float*)d_in[3];
    const float* qsc  = (const float*)d_in[4];
    const float* qbi  = (const float*)d_in[5];
    const float* ksc  = (const float*)d_in[6];
    const float* kbi  = (const float*)d_in[7];
    const float* relb = (const float*)d_in[8];
    const float* Wout = (const float*)d_in[9];
    const float* bout = (const float*)d_in[10];
    float* out = (float*)d_out;

    __half *wh_in_p, *wh_out_p;
    cudaGetSymbolAddress((void**)&wh_in_p, g_wh_in);
    cudaGetSymbolAddress((void**)&wh_out_p, g_wh_out);
    cudaFuncSetAttribute(attn_kernel, cudaFuncAttributeMaxDynamicSharedMemorySize, ATTN_SMEM);
    cudaFuncSetAttribute(mma_gemm<0>, cudaFuncAttributeMaxDynamicSharedMemorySize, GEMM_SMEM);
    cudaFuncSetAttribute(mma_gemm<1>, cudaFuncAttributeMaxDynamicSharedMemorySize, GEMM_SMEM);

    rms_conv_kernel<<<TT * NHEAD, 256>>>(x, w1);
    convw_kernel<<<(NQKV * CC / 4 + 255) / 256, 256>>>(Win, wh_in_p, NQKV * CC / 4);
    convw_kernel<<<(CC * CC / 4 + 255) / 256, 256>>>(Wout, wh_out_p, CC * CC / 4);
    mma_gemm<0><<<dim3(NQKV / 128, 256), 256, GEMM_SMEM>>>(x, binq, nullptr, NQKV);
    attn_kernel<<<dim3(NHEAD, SS / 8), 256, ATTN_SMEM>>>(qsc, qbi, ksc, kbi, relb);
    mma_gemm<1><<<dim3(CC / 128, 256), 256, GEMM_SMEM>>>(x, bout, out, CC);
}